// round 6
// baseline (speedup 1.0000x reference)
#include <cuda_runtime.h>
#include <cuda_bf16.h>
#include <math.h>
#include <stdint.h>

// ---------------- problem constants ----------------
#define B_   2
#define NQ_  8192
#define DM_  256
#define NH_  6
#define DH_  64
#define NL_  3
#define NP_  9
#define NHD_ (NH_*DH_)            // 384
#define NOFF_ (NH_*NL_*NP_*2)     // 324
#define NATT_ (NH_*NL_*NP_)       // 162
#define TOTHW_ 10080              // 7680+1920+480

// level tables
__device__ __constant__ int   c_W[3]   = {160, 80, 40};
__device__ __constant__ int   c_H[3]   = {48, 24, 12};
__device__ __constant__ int   c_OFF[3] = {0, 7680, 9600};
__device__ __constant__ float c_SX[3]  = {160.f/1280.f, 80.f/1280.f, 40.f/1280.f};
__device__ __constant__ float c_SY[3]  = {48.f/384.f, 24.f/384.f, 12.f/384.f};

// ---------------- scratch (no allocs allowed) ----------------
__device__ float g_v   [(size_t)B_ * TOTHW_ * NHD_];
__device__ float g_off [(size_t)B_ * NQ_ * NOFF_];
__device__ float g_attn[(size_t)B_ * NQ_ * NATT_];

// bf16 hi/lo planes
__device__ __nv_bfloat16 g_qh [(size_t)B_ * NQ_ * DM_];
__device__ __nv_bfloat16 g_ql [(size_t)B_ * NQ_ * DM_];
__device__ __nv_bfloat16 g_fh [(size_t)B_ * TOTHW_ * DM_];
__device__ __nv_bfloat16 g_fl [(size_t)B_ * TOTHW_ * DM_];
__device__ __nv_bfloat16 g_midh[(size_t)B_ * NQ_ * NHD_];
__device__ __nv_bfloat16 g_midl[(size_t)B_ * NQ_ * NHD_];

// transposed weights [N][K], packed: Wv(384x256) | Woff(324x256) | Wattn(162x256) | Wout(256x384)
#define WV_OFF  0
#define WOFF_OFF (384*256)
#define WATT_OFF (WOFF_OFF + 324*256)
#define WOUT_OFF (WATT_OFF + 162*256)
#define WTOT_ (WOUT_OFF + 256*384)
__device__ __nv_bfloat16 g_wh[WTOT_];
__device__ __nv_bfloat16 g_wl[WTOT_];

// ================= prep kernels =================
__global__ __launch_bounds__(256)
void add_split_kernel(const float* __restrict__ x, const float* __restrict__ pe,
                      __nv_bfloat16* __restrict__ oh, __nv_bfloat16* __restrict__ ol, int n4)
{
    int i = blockIdx.x * blockDim.x + threadIdx.x;
    if (i >= n4) return;
    float4 a = reinterpret_cast<const float4*>(x)[i];
    float4 b = reinterpret_cast<const float4*>(pe)[i];
    float v[4] = {a.x + b.x, a.y + b.y, a.z + b.z, a.w + b.w};
    __nv_bfloat16 h[4], l[4];
    #pragma unroll
    for (int j = 0; j < 4; j++) {
        h[j] = __float2bfloat16_rn(v[j]);
        l[j] = __float2bfloat16_rn(v[j] - __bfloat162float(h[j]));
    }
    *reinterpret_cast<uint2*>(oh + (size_t)i*4) = *reinterpret_cast<uint2*>(h);
    *reinterpret_cast<uint2*>(ol + (size_t)i*4) = *reinterpret_cast<uint2*>(l);
}

// transpose + split: in [R][C] fp32 -> out planes [C][R] bf16 (batched via strides)
__global__ __launch_bounds__(256)
void transpose_split_kernel(const float* __restrict__ in,
                            __nv_bfloat16* __restrict__ oh, __nv_bfloat16* __restrict__ ol,
                            int R, int C, long inStride, long outStride)
{
    __shared__ float t[32][33];
    const int b = blockIdx.z;
    const float* ip = in + (long)b * inStride;
    const int c0 = blockIdx.x * 32, r0 = blockIdx.y * 32;
    const int tx = threadIdx.x & 31, ty = threadIdx.x >> 5; // 32x8

    #pragma unroll
    for (int i = 0; i < 32; i += 8) {
        int r = r0 + ty + i, c = c0 + tx;
        t[ty + i][tx] = (r < R && c < C) ? ip[(long)r * C + c] : 0.f;
    }
    __syncthreads();
    #pragma unroll
    for (int i = 0; i < 32; i += 8) {
        int c = c0 + ty + i, r = r0 + tx;
        if (c < C && r < R) {
            float v = t[tx][ty + i];
            __nv_bfloat16 h = __float2bfloat16_rn(v);
            long o = (long)b * outStride + (long)c * R + r;
            oh[o] = h;
            ol[o] = __float2bfloat16_rn(v - __bfloat162float(h));
        }
    }
}

// ================= bf16 tensor-core GEMM =================
// C[M,N] = (Ah+Al)[M,K] @ (Bh+Bl)[N,K]^T + bias   (3-term split)
#define BM 128
#define BN 64
#define BK 32
#define A_TILE_B (BM*BK*2)                 // 8192 B per plane
#define B_TILE_B (BN*BK*2)                 // 4096 B per plane
#define STAGE_B  (2*A_TILE_B + 2*B_TILE_B) // 24576 B
#define GEMM_SMEM (2*STAGE_B)              // 49152 B

#define MMA16816(d, a, b0v, b1v) \
  asm volatile("mma.sync.aligned.m16n8k16.row.col.f32.bf16.bf16.f32 " \
    "{%0,%1,%2,%3},{%4,%5,%6,%7},{%8,%9},{%0,%1,%2,%3};" \
    : "+f"((d)[0]), "+f"((d)[1]), "+f"((d)[2]), "+f"((d)[3]) \
    : "r"((a)[0]), "r"((a)[1]), "r"((a)[2]), "r"((a)[3]), "r"(b0v), "r"(b1v))

__device__ __forceinline__ uint32_t swz(uint32_t off) {
    return off ^ ((off >> 3) & 0x30);
}
__device__ __forceinline__ void ldsm4(uint32_t (&r)[4], uint32_t addr) {
    asm volatile("ldmatrix.sync.aligned.m8n8.x4.shared.b16 {%0,%1,%2,%3}, [%4];"
        : "=r"(r[0]), "=r"(r[1]), "=r"(r[2]), "=r"(r[3]) : "r"(addr));
}
__device__ __forceinline__ void cp16(uint32_t dst, const void* src, bool pred) {
    int sz = pred ? 16 : 0;
    asm volatile("cp.async.cg.shared.global [%0], [%1], 16, %2;\n"
                 :: "r"(dst), "l"(src), "r"(sz));
}

__global__ __launch_bounds__(256, 2)
void bf16_gemm(const __nv_bfloat16* __restrict__ Ah, const __nv_bfloat16* __restrict__ Al,
               const __nv_bfloat16* __restrict__ Bh, const __nv_bfloat16* __restrict__ Bl,
               const float* __restrict__ bias, float* __restrict__ C,
               int M, int N, int K)
{
    extern __shared__ uint8_t sm8[];
    uint32_t smb;
    asm("{ .reg .u64 t; cvta.to.shared.u64 t, %1; cvt.u32.u64 %0, t; }" : "=r"(smb) : "l"(sm8));

    const int m0 = blockIdx.y * BM;
    const int n0 = blockIdx.x * BN;
    const int tid = threadIdx.x;
    const int lane = tid & 31, warp = tid >> 5;
    const int wm = warp & 3, wn = warp >> 2;
    const int r = lane >> 2, cc = lane & 3;

    float acc[2][4][4];
    #pragma unroll
    for (int i = 0; i < 2; i++)
        #pragma unroll
        for (int j = 0; j < 4; j++)
            #pragma unroll
            for (int t = 0; t < 4; t++) acc[i][j][t] = 0.f;

    const int nst = K / BK;

    auto LOAD = [&](int s, int buf) {
        uint32_t base = smb + buf * STAGE_B;
        const int k0 = s * BK;
        #pragma unroll
        for (int half = 0; half < 2; half++) {
            int c = tid + half * 256;
            int row = c >> 2, col = c & 3;
            bool p = (m0 + row) < M;
            long g = (long)(p ? (m0 + row) : 0) * K + k0 + col * 8;
            uint32_t so = swz((uint32_t)(row * 64 + col * 16));
            cp16(base + so, Ah + g, p);
            cp16(base + A_TILE_B + so, Al + g, p);
        }
        {
            int row = tid >> 2, col = tid & 3;
            bool p = (n0 + row) < N;
            long g = (long)(p ? (n0 + row) : 0) * K + k0 + col * 8;
            uint32_t so = swz((uint32_t)(row * 64 + col * 16));
            cp16(base + 2 * A_TILE_B + so, Bh + g, p);
            cp16(base + 2 * A_TILE_B + B_TILE_B + so, Bl + g, p);
        }
        asm volatile("cp.async.commit_group;\n" ::: "memory");
    };

    auto COMPUTE = [&](int buf) {
        uint32_t base = smb + buf * STAGE_B;
        #pragma unroll
        for (int kk = 0; kk < 2; kk++) {
            uint32_t ah[2][4], al[2][4], bh[2][4], bl[2][4];
            #pragma unroll
            for (int mt = 0; mt < 2; mt++) {
                int row = wm * 32 + mt * 16 + (lane & 15);
                uint32_t off = swz((uint32_t)(row * 64 + (kk * 2 + (lane >> 4)) * 16));
                ldsm4(ah[mt], base + off);
                ldsm4(al[mt], base + A_TILE_B + off);
            }
            #pragma unroll
            for (int nt2 = 0; nt2 < 2; nt2++) {
                int row = wn * 32 + nt2 * 16 + (lane & 15);
                uint32_t off = swz((uint32_t)(row * 64 + (kk * 2 + (lane >> 4)) * 16));
                ldsm4(bh[nt2], base + 2 * A_TILE_B + off);
                ldsm4(bl[nt2], base + 2 * A_TILE_B + B_TILE_B + off);
            }
            #pragma unroll
            for (int mt = 0; mt < 2; mt++)
                #pragma unroll
                for (int nt = 0; nt < 4; nt++) {
                    int n2 = nt >> 1, hv = nt & 1;
                    MMA16816(acc[mt][nt], ah[mt], bh[n2][hv], bh[n2][hv + 2]);
                    MMA16816(acc[mt][nt], al[mt], bh[n2][hv], bh[n2][hv + 2]);
                    MMA16816(acc[mt][nt], ah[mt], bl[n2][hv], bl[n2][hv + 2]);
                }
        }
    };

    LOAD(0, 0);
    for (int s = 0; s < nst; s++) {
        asm volatile("cp.async.wait_group 0;\n" ::: "memory");
        __syncthreads();
        if (s + 1 < nst) LOAD(s + 1, (s + 1) & 1);
        COMPUTE(s & 1);
    }

    // epilogue
    #pragma unroll
    for (int mt = 0; mt < 2; mt++) {
        int m = m0 + wm * 32 + mt * 16 + r;
        #pragma unroll
        for (int nt = 0; nt < 4; nt++) {
            int n = n0 + wn * 32 + nt * 8 + cc * 2;
            const float* d = acc[mt][nt];
            if (m < M) {
                if (n < N)     C[(long)m * N + n]     = d[0] + bias[n];
                if (n + 1 < N) C[(long)m * N + n + 1] = d[1] + bias[n + 1];
            }
            if (m + 8 < M) {
                if (n < N)     C[(long)(m + 8) * N + n]     = d[2] + bias[n];
                if (n + 1 < N) C[(long)(m + 8) * N + n + 1] = d[3] + bias[n + 1];
            }
        }
    }
}

// ---------------- sampler ----------------
__global__ __launch_bounds__(384)
void sample_kernel(const float* __restrict__ coor,
                   const float* __restrict__ cam2img,
                   const float* __restrict__ lidar2cam)
{
    const int q = blockIdx.x;
    const int b = blockIdx.y;
    const int tid = threadIdx.x;
    const int h = tid >> 6;
    const int d = tid & 63;

    __shared__ float s_uv[2];
    __shared__ float s_logit[NH_][NL_*NP_];
    __shared__ float s_w[NH_][NL_*NP_];
    __shared__ int   s_idx[NH_][NL_*NP_][4];
    __shared__ float s_bw[NH_][NL_*NP_][4];

    if (tid == 0) {
        const float* L  = lidar2cam + b * 16;
        const float* Kc = cam2img + b * 16;
        float p0 = coor[((long)b * NQ_ + q) * 3 + 0];
        float p1 = coor[((long)b * NQ_ + q) * 3 + 1];
        float p2 = coor[((long)b * NQ_ + q) * 3 + 2];
        float pc[3], pr[3];
        #pragma unroll
        for (int i = 0; i < 3; i++)
            pc[i] = L[i*4+0]*p0 + L[i*4+1]*p1 + L[i*4+2]*p2 + L[i*4+3];
        #pragma unroll
        for (int i = 0; i < 3; i++)
            pr[i] = Kc[i*4+0]*pc[0] + Kc[i*4+1]*pc[1] + Kc[i*4+2]*pc[2] + Kc[i*4+3];
        s_uv[0] = pr[0] / pr[2];
        s_uv[1] = pr[1] / pr[2];
    }
    __syncthreads();

    const long bq = (long)b * NQ_ + q;

    if (d < NL_*NP_) {
        const int j = d;
        const int l = j / NP_;
        const int p = j - l * NP_;

        s_logit[h][j] = g_attn[bq * NATT_ + h * (NL_*NP_) + j];

        const float* offp = &g_off[bq * NOFF_ + h * (NL_*NP_*2) + l * (NP_*2) + p * 2];
        float px = s_uv[0] * c_SX[l] + offp[0] - 0.5f;
        float py = s_uv[1] * c_SY[l] + offp[1] - 0.5f;
        float x0 = floorf(px), y0 = floorf(py);
        float fx = px - x0, fy = py - y0;
        const int wl = c_W[l], hl = c_H[l];
        const int base_l = b * TOTHW_ + c_OFF[l];

        #pragma unroll
        for (int c = 0; c < 4; c++) {
            int dx = c & 1, dy = c >> 1;
            float xi = x0 + dx, yi = y0 + dy;
            bool valid = (xi >= 0.f) && (xi < (float)wl) && (yi >= 0.f) && (yi < (float)hl);
            float wgt = (dx ? fx : 1.f - fx) * (dy ? fy : 1.f - fy);
            float xc = fminf(fmaxf(xi, 0.f), (float)(wl - 1));
            float yc = fminf(fmaxf(yi, 0.f), (float)(hl - 1));
            int pix = (int)yc * wl + (int)xc;
            s_idx[h][j][c] = (base_l + pix) * NHD_ + h * DH_;
            s_bw[h][j][c]  = valid ? wgt : 0.f;
        }
    }
    __syncthreads();

    if (d < NL_*NP_) {
        float mx = -1e30f;
        #pragma unroll
        for (int jj = 0; jj < NL_*NP_; jj++) mx = fmaxf(mx, s_logit[h][jj]);
        s_w[h][d] = expf(s_logit[h][d] - mx);
    }
    __syncthreads();

    float sum = 0.f;
    #pragma unroll
    for (int jj = 0; jj < NL_*NP_; jj++) sum += s_w[h][jj];
    const float rsum = 1.f / sum;

    float acc = 0.f;
    #pragma unroll 3
    for (int j = 0; j < NL_*NP_; j++) {
        float aw = s_w[h][j] * rsum;
        const int*   id = s_idx[h][j];
        const float* bw = s_bw[h][j];
        float s = bw[0] * g_v[id[0] + d]
                + bw[1] * g_v[id[1] + d]
                + bw[2] * g_v[id[2] + d]
                + bw[3] * g_v[id[3] + d];
        acc += aw * s;
    }
    long oidx = bq * NHD_ + h * DH_ + d;
    __nv_bfloat16 hh = __float2bfloat16_rn(acc);
    g_midh[oidx] = hh;
    g_midl[oidx] = __float2bfloat16_rn(acc - __bfloat162float(hh));
}

// ---------------- host launcher ----------------
extern "C" void kernel_launch(void* const* d_in, const int* in_sizes, int n_in,
                              void* d_out, int out_size)
{
    const float* x         = (const float*)d_in[0];
    const float* pe        = (const float*)d_in[1];
    const float* coor      = (const float*)d_in[2];
    const float* cam2img   = (const float*)d_in[3];
    const float* lidar2cam = (const float*)d_in[4];
    const float* feat0     = (const float*)d_in[5];
    const float* feat1     = (const float*)d_in[6];
    const float* feat2     = (const float*)d_in[7];
    const float* W_value   = (const float*)d_in[8];
    const float* b_value   = (const float*)d_in[9];
    const float* W_off     = (const float*)d_in[10];
    const float* b_off     = (const float*)d_in[11];
    const float* W_attn    = (const float*)d_in[12];
    const float* b_attn    = (const float*)d_in[13];
    const float* W_out     = (const float*)d_in[14];
    const float* b_out     = (const float*)d_in[15];
    float* out = (float*)d_out;

    float *pv, *poff, *pattn;
    __nv_bfloat16 *pqh, *pql, *pfh, *pfl, *pmidh, *pmidl, *pwh, *pwl;
    cudaGetSymbolAddress((void**)&pv, g_v);
    cudaGetSymbolAddress((void**)&poff, g_off);
    cudaGetSymbolAddress((void**)&pattn, g_attn);
    cudaGetSymbolAddress((void**)&pqh, g_qh);
    cudaGetSymbolAddress((void**)&pql, g_ql);
    cudaGetSymbolAddress((void**)&pfh, g_fh);
    cudaGetSymbolAddress((void**)&pfl, g_fl);
    cudaGetSymbolAddress((void**)&pmidh, g_midh);
    cudaGetSymbolAddress((void**)&pmidl, g_midl);
    cudaGetSymbolAddress((void**)&pwh, g_wh);
    cudaGetSymbolAddress((void**)&pwl, g_wl);

    static bool attrSet = false;
    if (!attrSet) {
        cudaFuncSetAttribute(bf16_gemm, cudaFuncAttributeMaxDynamicSharedMemorySize, GEMM_SMEM);
        attrSet = true;
    }

    const int hw[3]  = {7680, 1920, 480};
    const int off[3] = {0, 7680, 9600};
    const float* feats[3] = {feat0, feat1, feat2};

    // ---- prep: q = x + pe, split ----
    {
        int n4 = B_ * NQ_ * DM_ / 4;
        add_split_kernel<<<(n4 + 255) / 256, 256>>>(x, pe, pqh, pql, n4);
    }
    // ---- prep: feature transpose+split ([256, hw] -> [hw, 256]) ----
    for (int l = 0; l < 3; l++) {
        dim3 grid((hw[l] + 31) / 32, DM_ / 32, B_);
        transpose_split_kernel<<<grid, 256>>>(feats[l],
            pfh + (long)off[l] * DM_, pfl + (long)off[l] * DM_,
            DM_, hw[l], (long)DM_ * hw[l], (long)TOTHW_ * DM_);
    }
    // ---- prep: weight transpose+split ([K,N] -> [N,K]) ----
    {
        dim3 g1((NHD_ + 31) / 32, DM_ / 32, 1);
        transpose_split_kernel<<<g1, 256>>>(W_value, pwh + WV_OFF, pwl + WV_OFF, DM_, NHD_, 0, 0);
        dim3 g2((NOFF_ + 31) / 32, DM_ / 32, 1);
        transpose_split_kernel<<<g2, 256>>>(W_off, pwh + WOFF_OFF, pwl + WOFF_OFF, DM_, NOFF_, 0, 0);
        dim3 g3((NATT_ + 31) / 32, DM_ / 32, 1);
        transpose_split_kernel<<<g3, 256>>>(W_attn, pwh + WATT_OFF, pwl + WATT_OFF, DM_, NATT_, 0, 0);
        dim3 g4((DM_ + 31) / 32, NHD_ / 32, 1);
        transpose_split_kernel<<<g4, 256>>>(W_out, pwh + WOUT_OFF, pwl + WOUT_OFF, NHD_, DM_, 0, 0);
    }

    // ---- GEMM 1: value projection (single fused launch, M = B*TOTHW) ----
    {
        dim3 grid(NHD_ / BN, (B_ * TOTHW_ + BM - 1) / BM);
        bf16_gemm<<<grid, 256, GEMM_SMEM>>>(pfh, pfl, pwh + WV_OFF, pwl + WV_OFF,
                                            b_value, pv, B_ * TOTHW_, NHD_, DM_);
    }
    // ---- GEMM 2: offsets ----
    {
        dim3 grid((NOFF_ + BN - 1) / BN, (B_ * NQ_) / BM);
        bf16_gemm<<<grid, 256, GEMM_SMEM>>>(pqh, pql, pwh + WOFF_OFF, pwl + WOFF_OFF,
                                            b_off, poff, B_ * NQ_, NOFF_, DM_);
    }
    // ---- GEMM 3: attention logits ----
    {
        dim3 grid((NATT_ + BN - 1) / BN, (B_ * NQ_) / BM);
        bf16_gemm<<<grid, 256, GEMM_SMEM>>>(pqh, pql, pwh + WATT_OFF, pwl + WATT_OFF,
                                            b_attn, pattn, B_ * NQ_, NATT_, DM_);
    }
    // ---- sampler ----
    {
        dim3 grid(NQ_, B_);
        sample_kernel<<<grid, 384>>>(coor, cam2img, lidar2cam);
    }
    // ---- GEMM 4: output projection ----
    {
        dim3 grid(DM_ / BN, (B_ * NQ_) / BM);
        bf16_gemm<<<grid, 256, GEMM_SMEM>>>(pmidh, pmidl, pwh + WOUT_OFF, pwl + WOUT_OFF,
                                            b_out, out, B_ * NQ_, DM_, NHD_);
    }
}

// round 7
// speedup vs baseline: 1.0059x; 1.0059x over previous
#include <cuda_runtime.h>
#include <cuda_bf16.h>
#include <cuda_fp16.h>
#include <math.h>
#include <stdint.h>

// ---------------- problem constants ----------------
#define B_   2
#define NQ_  8192
#define DM_  256
#define NH_  6
#define DH_  64
#define NL_  3
#define NP_  9
#define NHD_ (NH_*DH_)            // 384
#define NOFF_ (NH_*NL_*NP_*2)     // 324
#define NATT_ (NH_*NL_*NP_)       // 162
#define TOTHW_ 10080              // 7680+1920+480

// level tables
__device__ __constant__ int   c_W[3]   = {160, 80, 40};
__device__ __constant__ int   c_H[3]   = {48, 24, 12};
__device__ __constant__ int   c_OFF[3] = {0, 7680, 9600};
__device__ __constant__ float c_SX[3]  = {160.f/1280.f, 80.f/1280.f, 40.f/1280.f};
__device__ __constant__ float c_SY[3]  = {48.f/384.f, 24.f/384.f, 12.f/384.f};

// ---------------- scratch (no allocs allowed) ----------------
__device__ __half g_vh16[(size_t)B_ * TOTHW_ * NHD_];   // value projection in fp16
__device__ float g_off [(size_t)B_ * NQ_ * NOFF_];
__device__ float g_attn[(size_t)B_ * NQ_ * NATT_];

// bf16 hi/lo planes
__device__ __nv_bfloat16 g_qh [(size_t)B_ * NQ_ * DM_];
__device__ __nv_bfloat16 g_ql [(size_t)B_ * NQ_ * DM_];
__device__ __nv_bfloat16 g_fh [(size_t)B_ * TOTHW_ * DM_];
__device__ __nv_bfloat16 g_fl [(size_t)B_ * TOTHW_ * DM_];
__device__ __nv_bfloat16 g_midh[(size_t)B_ * NQ_ * NHD_];
__device__ __nv_bfloat16 g_midl[(size_t)B_ * NQ_ * NHD_];

// transposed weights [N][K], packed
#define WV_OFF  0
#define WOFF_OFF (384*256)
#define WATT_OFF (WOFF_OFF + 324*256)
#define WOUT_OFF (WATT_OFF + 162*256)
#define WTOT_ (WOUT_OFF + 256*384)
__device__ __nv_bfloat16 g_wh[WTOT_];
__device__ __nv_bfloat16 g_wl[WTOT_];

// ================= prep kernels =================
__global__ __launch_bounds__(256)
void add_split_kernel(const float* __restrict__ x, const float* __restrict__ pe,
                      __nv_bfloat16* __restrict__ oh, __nv_bfloat16* __restrict__ ol, int n4)
{
    int i = blockIdx.x * blockDim.x + threadIdx.x;
    if (i >= n4) return;
    float4 a = reinterpret_cast<const float4*>(x)[i];
    float4 b = reinterpret_cast<const float4*>(pe)[i];
    float v[4] = {a.x + b.x, a.y + b.y, a.z + b.z, a.w + b.w};
    __nv_bfloat16 h[4], l[4];
    #pragma unroll
    for (int j = 0; j < 4; j++) {
        h[j] = __float2bfloat16_rn(v[j]);
        l[j] = __float2bfloat16_rn(v[j] - __bfloat162float(h[j]));
    }
    *reinterpret_cast<uint2*>(oh + (size_t)i*4) = *reinterpret_cast<uint2*>(h);
    *reinterpret_cast<uint2*>(ol + (size_t)i*4) = *reinterpret_cast<uint2*>(l);
}

// transpose + split: in [R][C] fp32 -> out planes [C][R] bf16 (batched via strides)
__global__ __launch_bounds__(256)
void transpose_split_kernel(const float* __restrict__ in,
                            __nv_bfloat16* __restrict__ oh, __nv_bfloat16* __restrict__ ol,
                            int R, int C, long inStride, long outStride)
{
    __shared__ float t[32][33];
    const int b = blockIdx.z;
    const float* ip = in + (long)b * inStride;
    const int c0 = blockIdx.x * 32, r0 = blockIdx.y * 32;
    const int tx = threadIdx.x & 31, ty = threadIdx.x >> 5; // 32x8

    #pragma unroll
    for (int i = 0; i < 32; i += 8) {
        int r = r0 + ty + i, c = c0 + tx;
        t[ty + i][tx] = (r < R && c < C) ? ip[(long)r * C + c] : 0.f;
    }
    __syncthreads();
    #pragma unroll
    for (int i = 0; i < 32; i += 8) {
        int c = c0 + ty + i, r = r0 + tx;
        if (c < C && r < R) {
            float v = t[tx][ty + i];
            __nv_bfloat16 h = __float2bfloat16_rn(v);
            long o = (long)b * outStride + (long)c * R + r;
            oh[o] = h;
            ol[o] = __float2bfloat16_rn(v - __bfloat162float(h));
        }
    }
}

// ================= bf16 tensor-core GEMM =================
// C[M,N] = (Ah+Al)[M,K] @ (Bh+Bl)[N,K]^T + bias   (3-term split)
// halfOut: 0 -> fp32 C, 1 -> fp16 C
#define BM 128
#define BN 64
#define BK 32
#define A_TILE_B (BM*BK*2)
#define B_TILE_B (BN*BK*2)
#define STAGE_B  (2*A_TILE_B + 2*B_TILE_B)
#define GEMM_SMEM (2*STAGE_B)

#define MMA16816(d, a, b0v, b1v) \
  asm volatile("mma.sync.aligned.m16n8k16.row.col.f32.bf16.bf16.f32 " \
    "{%0,%1,%2,%3},{%4,%5,%6,%7},{%8,%9},{%0,%1,%2,%3};" \
    : "+f"((d)[0]), "+f"((d)[1]), "+f"((d)[2]), "+f"((d)[3]) \
    : "r"((a)[0]), "r"((a)[1]), "r"((a)[2]), "r"((a)[3]), "r"(b0v), "r"(b1v))

__device__ __forceinline__ uint32_t swz(uint32_t off) {
    return off ^ ((off >> 3) & 0x30);
}
__device__ __forceinline__ void ldsm4(uint32_t (&r)[4], uint32_t addr) {
    asm volatile("ldmatrix.sync.aligned.m8n8.x4.shared.b16 {%0,%1,%2,%3}, [%4];"
        : "=r"(r[0]), "=r"(r[1]), "=r"(r[2]), "=r"(r[3]) : "r"(addr));
}
__device__ __forceinline__ void cp16(uint32_t dst, const void* src, bool pred) {
    int sz = pred ? 16 : 0;
    asm volatile("cp.async.cg.shared.global [%0], [%1], 16, %2;\n"
                 :: "r"(dst), "l"(src), "r"(sz));
}

__global__ __launch_bounds__(256, 2)
void bf16_gemm(const __nv_bfloat16* __restrict__ Ah, const __nv_bfloat16* __restrict__ Al,
               const __nv_bfloat16* __restrict__ Bh, const __nv_bfloat16* __restrict__ Bl,
               const float* __restrict__ bias, void* __restrict__ Cv,
               int M, int N, int K, int halfOut)
{
    extern __shared__ uint8_t sm8[];
    uint32_t smb;
    asm("{ .reg .u64 t; cvta.to.shared.u64 t, %1; cvt.u32.u64 %0, t; }" : "=r"(smb) : "l"(sm8));

    const int m0 = blockIdx.y * BM;
    const int n0 = blockIdx.x * BN;
    const int tid = threadIdx.x;
    const int lane = tid & 31, warp = tid >> 5;
    const int wm = warp & 3, wn = warp >> 2;
    const int r = lane >> 2, cc = lane & 3;

    float acc[2][4][4];
    #pragma unroll
    for (int i = 0; i < 2; i++)
        #pragma unroll
        for (int j = 0; j < 4; j++)
            #pragma unroll
            for (int t = 0; t < 4; t++) acc[i][j][t] = 0.f;

    const int nst = K / BK;

    auto LOAD = [&](int s, int buf) {
        uint32_t base = smb + buf * STAGE_B;
        const int k0 = s * BK;
        #pragma unroll
        for (int half = 0; half < 2; half++) {
            int c = tid + half * 256;
            int row = c >> 2, col = c & 3;
            bool p = (m0 + row) < M;
            long g = (long)(p ? (m0 + row) : 0) * K + k0 + col * 8;
            uint32_t so = swz((uint32_t)(row * 64 + col * 16));
            cp16(base + so, Ah + g, p);
            cp16(base + A_TILE_B + so, Al + g, p);
        }
        {
            int row = tid >> 2, col = tid & 3;
            bool p = (n0 + row) < N;
            long g = (long)(p ? (n0 + row) : 0) * K + k0 + col * 8;
            uint32_t so = swz((uint32_t)(row * 64 + col * 16));
            cp16(base + 2 * A_TILE_B + so, Bh + g, p);
            cp16(base + 2 * A_TILE_B + B_TILE_B + so, Bl + g, p);
        }
        asm volatile("cp.async.commit_group;\n" ::: "memory");
    };

    auto COMPUTE = [&](int buf) {
        uint32_t base = smb + buf * STAGE_B;
        #pragma unroll
        for (int kk = 0; kk < 2; kk++) {
            uint32_t ah[2][4], al[2][4], bh[2][4], bl[2][4];
            #pragma unroll
            for (int mt = 0; mt < 2; mt++) {
                int row = wm * 32 + mt * 16 + (lane & 15);
                uint32_t off = swz((uint32_t)(row * 64 + (kk * 2 + (lane >> 4)) * 16));
                ldsm4(ah[mt], base + off);
                ldsm4(al[mt], base + A_TILE_B + off);
            }
            #pragma unroll
            for (int nt2 = 0; nt2 < 2; nt2++) {
                int row = wn * 32 + nt2 * 16 + (lane & 15);
                uint32_t off = swz((uint32_t)(row * 64 + (kk * 2 + (lane >> 4)) * 16));
                ldsm4(bh[nt2], base + 2 * A_TILE_B + off);
                ldsm4(bl[nt2], base + 2 * A_TILE_B + B_TILE_B + off);
            }
            #pragma unroll
            for (int mt = 0; mt < 2; mt++)
                #pragma unroll
                for (int nt = 0; nt < 4; nt++) {
                    int n2 = nt >> 1, hv = nt & 1;
                    MMA16816(acc[mt][nt], ah[mt], bh[n2][hv], bh[n2][hv + 2]);
                    MMA16816(acc[mt][nt], al[mt], bh[n2][hv], bh[n2][hv + 2]);
                    MMA16816(acc[mt][nt], ah[mt], bl[n2][hv], bl[n2][hv + 2]);
                }
        }
    };

    LOAD(0, 0);
    for (int s = 0; s < nst; s++) {
        asm volatile("cp.async.wait_group 0;\n" ::: "memory");
        __syncthreads();
        if (s + 1 < nst) LOAD(s + 1, (s + 1) & 1);
        COMPUTE(s & 1);
    }

    // epilogue
    if (halfOut) {
        __half* C = (__half*)Cv;
        #pragma unroll
        for (int mt = 0; mt < 2; mt++) {
            int m = m0 + wm * 32 + mt * 16 + r;
            #pragma unroll
            for (int nt = 0; nt < 4; nt++) {
                int n = n0 + wn * 32 + nt * 8 + cc * 2;
                const float* d = acc[mt][nt];
                if (n + 1 < N) {
                    float b0 = bias[n], b1 = bias[n + 1];
                    if (m < M)
                        *(__half2*)&C[(long)m * N + n] = __floats2half2_rn(d[0] + b0, d[1] + b1);
                    if (m + 8 < M)
                        *(__half2*)&C[(long)(m + 8) * N + n] = __floats2half2_rn(d[2] + b0, d[3] + b1);
                } else if (n < N) {
                    float b0 = bias[n];
                    if (m < M)     C[(long)m * N + n]       = __float2half_rn(d[0] + b0);
                    if (m + 8 < M) C[(long)(m + 8) * N + n] = __float2half_rn(d[2] + b0);
                }
            }
        }
    } else {
        float* C = (float*)Cv;
        #pragma unroll
        for (int mt = 0; mt < 2; mt++) {
            int m = m0 + wm * 32 + mt * 16 + r;
            #pragma unroll
            for (int nt = 0; nt < 4; nt++) {
                int n = n0 + wn * 32 + nt * 8 + cc * 2;
                const float* d = acc[mt][nt];
                if (m < M) {
                    if (n < N)     C[(long)m * N + n]     = d[0] + bias[n];
                    if (n + 1 < N) C[(long)m * N + n + 1] = d[1] + bias[n + 1];
                }
                if (m + 8 < M) {
                    if (n < N)     C[(long)(m + 8) * N + n]     = d[2] + bias[n];
                    if (n + 1 < N) C[(long)(m + 8) * N + n + 1] = d[3] + bias[n + 1];
                }
            }
        }
    }
}

// ---------------- sampler (fp16 value gathers) ----------------
__global__ __launch_bounds__(384)
void sample_kernel(const float* __restrict__ coor,
                   const float* __restrict__ cam2img,
                   const float* __restrict__ lidar2cam)
{
    const int q = blockIdx.x;
    const int b = blockIdx.y;
    const int tid = threadIdx.x;
    const int h = tid >> 6;
    const int d = tid & 63;

    __shared__ float s_uv[2];
    __shared__ float s_logit[NH_][NL_*NP_];
    __shared__ float s_w[NH_][NL_*NP_];
    __shared__ int   s_idx[NH_][NL_*NP_][4];
    __shared__ float s_bw[NH_][NL_*NP_][4];

    if (tid == 0) {
        const float* L  = lidar2cam + b * 16;
        const float* Kc = cam2img + b * 16;
        float p0 = coor[((long)b * NQ_ + q) * 3 + 0];
        float p1 = coor[((long)b * NQ_ + q) * 3 + 1];
        float p2 = coor[((long)b * NQ_ + q) * 3 + 2];
        float pc[3], pr[3];
        #pragma unroll
        for (int i = 0; i < 3; i++)
            pc[i] = L[i*4+0]*p0 + L[i*4+1]*p1 + L[i*4+2]*p2 + L[i*4+3];
        #pragma unroll
        for (int i = 0; i < 3; i++)
            pr[i] = Kc[i*4+0]*pc[0] + Kc[i*4+1]*pc[1] + Kc[i*4+2]*pc[2] + Kc[i*4+3];
        s_uv[0] = pr[0] / pr[2];
        s_uv[1] = pr[1] / pr[2];
    }
    __syncthreads();

    const long bq = (long)b * NQ_ + q;

    if (d < NL_*NP_) {
        const int j = d;
        const int l = j / NP_;
        const int p = j - l * NP_;

        s_logit[h][j] = g_attn[bq * NATT_ + h * (NL_*NP_) + j];

        const float* offp = &g_off[bq * NOFF_ + h * (NL_*NP_*2) + l * (NP_*2) + p * 2];
        float px = s_uv[0] * c_SX[l] + offp[0] - 0.5f;
        float py = s_uv[1] * c_SY[l] + offp[1] - 0.5f;
        float x0 = floorf(px), y0 = floorf(py);
        float fx = px - x0, fy = py - y0;
        const int wl = c_W[l], hl = c_H[l];
        const int base_l = b * TOTHW_ + c_OFF[l];

        #pragma unroll
        for (int c = 0; c < 4; c++) {
            int dx = c & 1, dy = c >> 1;
            float xi = x0 + dx, yi = y0 + dy;
            bool valid = (xi >= 0.f) && (xi < (float)wl) && (yi >= 0.f) && (yi < (float)hl);
            float wgt = (dx ? fx : 1.f - fx) * (dy ? fy : 1.f - fy);
            float xc = fminf(fmaxf(xi, 0.f), (float)(wl - 1));
            float yc = fminf(fmaxf(yi, 0.f), (float)(hl - 1));
            int pix = (int)yc * wl + (int)xc;
            s_idx[h][j][c] = (base_l + pix) * NHD_ + h * DH_;
            s_bw[h][j][c]  = valid ? wgt : 0.f;
        }
    }
    __syncthreads();

    if (d < NL_*NP_) {
        float mx = -1e30f;
        #pragma unroll
        for (int jj = 0; jj < NL_*NP_; jj++) mx = fmaxf(mx, s_logit[h][jj]);
        s_w[h][d] = expf(s_logit[h][d] - mx);
    }
    __syncthreads();

    float sum = 0.f;
    #pragma unroll
    for (int jj = 0; jj < NL_*NP_; jj++) sum += s_w[h][jj];
    const float rsum = 1.f / sum;

    float acc = 0.f;
    #pragma unroll 3
    for (int j = 0; j < NL_*NP_; j++) {
        float aw = s_w[h][j] * rsum;
        const int*   id = s_idx[h][j];
        const float* bw = s_bw[h][j];
        float s = bw[0] * __half2float(g_vh16[id[0] + d])
                + bw[1] * __half2float(g_vh16[id[1] + d])
                + bw[2] * __half2float(g_vh16[id[2] + d])
                + bw[3] * __half2float(g_vh16[id[3] + d]);
        acc += aw * s;
    }
    long oidx = bq * NHD_ + h * DH_ + d;
    __nv_bfloat16 hh = __float2bfloat16_rn(acc);
    g_midh[oidx] = hh;
    g_midl[oidx] = __float2bfloat16_rn(acc - __bfloat162float(hh));
}

// ---------------- host launcher ----------------
extern "C" void kernel_launch(void* const* d_in, const int* in_sizes, int n_in,
                              void* d_out, int out_size)
{
    const float* x         = (const float*)d_in[0];
    const float* pe        = (const float*)d_in[1];
    const float* coor      = (const float*)d_in[2];
    const float* cam2img   = (const float*)d_in[3];
    const float* lidar2cam = (const float*)d_in[4];
    const float* feat0     = (const float*)d_in[5];
    const float* feat1     = (const float*)d_in[6];
    const float* feat2     = (const float*)d_in[7];
    const float* W_value   = (const float*)d_in[8];
    const float* b_value   = (const float*)d_in[9];
    const float* W_off     = (const float*)d_in[10];
    const float* b_off     = (const float*)d_in[11];
    const float* W_attn    = (const float*)d_in[12];
    const float* b_attn    = (const float*)d_in[13];
    const float* W_out     = (const float*)d_in[14];
    const float* b_out     = (const float*)d_in[15];
    float* out = (float*)d_out;

    float *poff, *pattn;
    __half* pv16;
    __nv_bfloat16 *pqh, *pql, *pfh, *pfl, *pmidh, *pmidl, *pwh, *pwl;
    cudaGetSymbolAddress((void**)&pv16, g_vh16);
    cudaGetSymbolAddress((void**)&poff, g_off);
    cudaGetSymbolAddress((void**)&pattn, g_attn);
    cudaGetSymbolAddress((void**)&pqh, g_qh);
    cudaGetSymbolAddress((void**)&pql, g_ql);
    cudaGetSymbolAddress((void**)&pfh, g_fh);
    cudaGetSymbolAddress((void**)&pfl, g_fl);
    cudaGetSymbolAddress((void**)&pmidh, g_midh);
    cudaGetSymbolAddress((void**)&pmidl, g_midl);
    cudaGetSymbolAddress((void**)&pwh, g_wh);
    cudaGetSymbolAddress((void**)&pwl, g_wl);

    static bool attrSet = false;
    if (!attrSet) {
        cudaFuncSetAttribute(bf16_gemm, cudaFuncAttributeMaxDynamicSharedMemorySize, GEMM_SMEM);
        attrSet = true;
    }

    const int hw[3]  = {7680, 1920, 480};
    const int off[3] = {0, 7680, 9600};
    const float* feats[3] = {feat0, feat1, feat2};

    // ---- prep: q = x + pe, split ----
    {
        int n4 = B_ * NQ_ * DM_ / 4;
        add_split_kernel<<<(n4 + 255) / 256, 256>>>(x, pe, pqh, pql, n4);
    }
    // ---- prep: feature transpose+split ([256, hw] -> [hw, 256]) ----
    for (int l = 0; l < 3; l++) {
        dim3 grid((hw[l] + 31) / 32, DM_ / 32, B_);
        transpose_split_kernel<<<grid, 256>>>(feats[l],
            pfh + (long)off[l] * DM_, pfl + (long)off[l] * DM_,
            DM_, hw[l], (long)DM_ * hw[l], (long)TOTHW_ * DM_);
    }
    // ---- prep: weight transpose+split ([K,N] -> [N,K]) ----
    {
        dim3 g1((NHD_ + 31) / 32, DM_ / 32, 1);
        transpose_split_kernel<<<g1, 256>>>(W_value, pwh + WV_OFF, pwl + WV_OFF, DM_, NHD_, 0, 0);
        dim3 g2((NOFF_ + 31) / 32, DM_ / 32, 1);
        transpose_split_kernel<<<g2, 256>>>(W_off, pwh + WOFF_OFF, pwl + WOFF_OFF, DM_, NOFF_, 0, 0);
        dim3 g3((NATT_ + 31) / 32, DM_ / 32, 1);
        transpose_split_kernel<<<g3, 256>>>(W_attn, pwh + WATT_OFF, pwl + WATT_OFF, DM_, NATT_, 0, 0);
        dim3 g4((DM_ + 31) / 32, NHD_ / 32, 1);
        transpose_split_kernel<<<g4, 256>>>(W_out, pwh + WOUT_OFF, pwl + WOUT_OFF, NHD_, DM_, 0, 0);
    }

    // ---- GEMM 1: value projection (fp16 output) ----
    {
        dim3 grid(NHD_ / BN, (B_ * TOTHW_ + BM - 1) / BM);
        bf16_gemm<<<grid, 256, GEMM_SMEM>>>(pfh, pfl, pwh + WV_OFF, pwl + WV_OFF,
                                            b_value, pv16, B_ * TOTHW_, NHD_, DM_, 1);
    }
    // ---- GEMM 2: offsets ----
    {
        dim3 grid((NOFF_ + BN - 1) / BN, (B_ * NQ_) / BM);
        bf16_gemm<<<grid, 256, GEMM_SMEM>>>(pqh, pql, pwh + WOFF_OFF, pwl + WOFF_OFF,
                                            b_off, poff, B_ * NQ_, NOFF_, DM_, 0);
    }
    // ---- GEMM 3: attention logits ----
    {
        dim3 grid((NATT_ + BN - 1) / BN, (B_ * NQ_) / BM);
        bf16_gemm<<<grid, 256, GEMM_SMEM>>>(pqh, pql, pwh + WATT_OFF, pwl + WATT_OFF,
                                            b_attn, pattn, B_ * NQ_, NATT_, DM_, 0);
    }
    // ---- sampler ----
    {
        dim3 grid(NQ_, B_);
        sample_kernel<<<grid, 384>>>(coor, cam2img, lidar2cam);
    }
    // ---- GEMM 4: output projection ----
    {
        dim3 grid(DM_ / BN, (B_ * NQ_) / BM);
        bf16_gemm<<<grid, 256, GEMM_SMEM>>>(pmidh, pmidl, pwh + WOUT_OFF, pwl + WOUT_OFF,
                                            b_out, out, B_ * NQ_, DM_, NHD_, 0);
    }
}

// round 8
// speedup vs baseline: 1.3924x; 1.3842x over previous
#include <cuda_runtime.h>
#include <cuda_bf16.h>
#include <cuda_fp16.h>
#include <math.h>
#include <stdint.h>

// ---------------- problem constants ----------------
#define B_   2
#define NQ_  8192
#define DM_  256
#define NH_  6
#define DH_  64
#define NL_  3
#define NP_  9
#define NHD_ (NH_*DH_)            // 384
#define NOFF_ (NH_*NL_*NP_*2)     // 324
#define NATT_ (NH_*NL_*NP_)       // 162
#define NOA_  (NOFF_ + NATT_)     // 486 (offsets | attn combined)
#define TOTHW_ 10080              // 7680+1920+480

// level tables
__device__ __constant__ int   c_W[3]   = {160, 80, 40};
__device__ __constant__ int   c_H[3]   = {48, 24, 12};
__device__ __constant__ int   c_OFF[3] = {0, 7680, 9600};
__device__ __constant__ float c_SX[3]  = {160.f/1280.f, 80.f/1280.f, 40.f/1280.f};
__device__ __constant__ float c_SY[3]  = {48.f/384.f, 24.f/384.f, 12.f/384.f};

// ---------------- scratch (no allocs allowed) ----------------
__device__ __half g_vh16[(size_t)B_ * TOTHW_ * NHD_];   // value projection in fp16
__device__ float g_oa  [(size_t)B_ * NQ_ * NOA_];       // offsets(324) | attn(162)
__device__ float g_boa [NOA_];                          // combined bias

// bf16 hi/lo planes
__device__ __nv_bfloat16 g_qh [(size_t)B_ * NQ_ * DM_];
__device__ __nv_bfloat16 g_ql [(size_t)B_ * NQ_ * DM_];
__device__ __nv_bfloat16 g_fh [(size_t)B_ * TOTHW_ * DM_];
__device__ __nv_bfloat16 g_fl [(size_t)B_ * TOTHW_ * DM_];
__device__ __nv_bfloat16 g_midh[(size_t)B_ * NQ_ * NHD_];
__device__ __nv_bfloat16 g_midl[(size_t)B_ * NQ_ * NHD_];

// transposed weights [N][K]: Wv(384x256) | Woa(486x256) | Wout(256x384)
#define WV_OFF   0
#define WOA_OFF  (384*256)
#define WOUT_OFF (WOA_OFF + NOA_*256)
#define WTOT_    (WOUT_OFF + 256*384)
__device__ __nv_bfloat16 g_wh[WTOT_];
__device__ __nv_bfloat16 g_wl[WTOT_];

// ================= prep kernels =================
__global__ __launch_bounds__(256)
void add_split_kernel(const float* __restrict__ x, const float* __restrict__ pe,
                      __nv_bfloat16* __restrict__ oh, __nv_bfloat16* __restrict__ ol, int n4)
{
    int i = blockIdx.x * blockDim.x + threadIdx.x;
    if (i >= n4) return;
    float4 a = reinterpret_cast<const float4*>(x)[i];
    float4 b = reinterpret_cast<const float4*>(pe)[i];
    float v[4] = {a.x + b.x, a.y + b.y, a.z + b.z, a.w + b.w};
    __nv_bfloat16 h[4], l[4];
    #pragma unroll
    for (int j = 0; j < 4; j++) {
        h[j] = __float2bfloat16_rn(v[j]);
        l[j] = __float2bfloat16_rn(v[j] - __bfloat162float(h[j]));
    }
    *reinterpret_cast<uint2*>(oh + (size_t)i*4) = *reinterpret_cast<uint2*>(h);
    *reinterpret_cast<uint2*>(ol + (size_t)i*4) = *reinterpret_cast<uint2*>(l);
}

// transpose + split features: in [R][C] fp32 -> out planes [C][R] bf16 (batched)
__global__ __launch_bounds__(256)
void transpose_split_kernel(const float* __restrict__ in,
                            __nv_bfloat16* __restrict__ oh, __nv_bfloat16* __restrict__ ol,
                            int R, int C, long inStride, long outStride)
{
    __shared__ float t[32][33];
    const int b = blockIdx.z;
    const float* ip = in + (long)b * inStride;
    const int c0 = blockIdx.x * 32, r0 = blockIdx.y * 32;
    const int tx = threadIdx.x & 31, ty = threadIdx.x >> 5;

    #pragma unroll
    for (int i = 0; i < 32; i += 8) {
        int r = r0 + ty + i, c = c0 + tx;
        t[ty + i][tx] = (r < R && c < C) ? ip[(long)r * C + c] : 0.f;
    }
    __syncthreads();
    #pragma unroll
    for (int i = 0; i < 32; i += 8) {
        int c = c0 + ty + i, r = r0 + tx;
        if (c < C && r < R) {
            float v = t[tx][ty + i];
            __nv_bfloat16 h = __float2bfloat16_rn(v);
            long o = (long)b * outStride + (long)c * R + r;
            oh[o] = h;
            ol[o] = __float2bfloat16_rn(v - __bfloat162float(h));
        }
    }
}

// fused: all 4 weight transposes (+split) and bias concat in one launch
__global__ __launch_bounds__(256)
void prep_weights_kernel(const float* __restrict__ Wv, const float* __restrict__ Woff,
                         const float* __restrict__ Wattn, const float* __restrict__ Wout,
                         const float* __restrict__ boff, const float* __restrict__ battn)
{
    const int z = blockIdx.z;
    if (z == 4) {
        if (blockIdx.y != 0 || blockIdx.x > 1) return;
        int i = blockIdx.x * 256 + threadIdx.x;
        if (i < NOFF_) g_boa[i] = boff[i];
        else if (i < NOA_) g_boa[i] = battn[i - NOFF_];
        return;
    }
    int R, C; const float* in; long base; int rowOff = 0;
    if (z == 0)      { in = Wv;    R = 256; C = 384; base = WV_OFF; }
    else if (z == 1) { in = Woff;  R = 256; C = 324; base = WOA_OFF; }
    else if (z == 2) { in = Wattn; R = 256; C = 162; base = WOA_OFF; rowOff = 324; }
    else             { in = Wout;  R = 384; C = 256; base = WOUT_OFF; }

    const int c0 = blockIdx.x * 32, r0 = blockIdx.y * 32;
    if (c0 >= C || r0 >= R) return;

    __shared__ float t[32][33];
    const int tx = threadIdx.x & 31, ty = threadIdx.x >> 5;
    #pragma unroll
    for (int i = 0; i < 32; i += 8) {
        int r = r0 + ty + i, c = c0 + tx;
        t[ty + i][tx] = (r < R && c < C) ? in[(long)r * C + c] : 0.f;
    }
    __syncthreads();
    #pragma unroll
    for (int i = 0; i < 32; i += 8) {
        int c = c0 + ty + i, r = r0 + tx;
        if (c < C && r < R) {
            float v = t[tx][ty + i];
            __nv_bfloat16 h = __float2bfloat16_rn(v);
            long o = base + (long)(rowOff + c) * R + r;
            g_wh[o] = h;
            g_wl[o] = __float2bfloat16_rn(v - __bfloat162float(h));
        }
    }
}

// ================= bf16 tensor-core GEMM (3-stage cp.async pipeline) =================
#define BM 128
#define BN 64
#define BK 32
#define A_TILE_B (BM*BK*2)
#define B_TILE_B (BN*BK*2)
#define STAGE_B  (2*A_TILE_B + 2*B_TILE_B)   // 24576
#define NSTAGE 3
#define GEMM_SMEM (NSTAGE*STAGE_B)           // 73728

#define MMA16816(d, a, b0v, b1v) \
  asm volatile("mma.sync.aligned.m16n8k16.row.col.f32.bf16.bf16.f32 " \
    "{%0,%1,%2,%3},{%4,%5,%6,%7},{%8,%9},{%0,%1,%2,%3};" \
    : "+f"((d)[0]), "+f"((d)[1]), "+f"((d)[2]), "+f"((d)[3]) \
    : "r"((a)[0]), "r"((a)[1]), "r"((a)[2]), "r"((a)[3]), "r"(b0v), "r"(b1v))

__device__ __forceinline__ uint32_t swz(uint32_t off) {
    return off ^ ((off >> 3) & 0x30);
}
__device__ __forceinline__ void ldsm4(uint32_t (&r)[4], uint32_t addr) {
    asm volatile("ldmatrix.sync.aligned.m8n8.x4.shared.b16 {%0,%1,%2,%3}, [%4];"
        : "=r"(r[0]), "=r"(r[1]), "=r"(r[2]), "=r"(r[3]) : "r"(addr));
}
__device__ __forceinline__ void cp16(uint32_t dst, const void* src, bool pred) {
    int sz = pred ? 16 : 0;
    asm volatile("cp.async.cg.shared.global [%0], [%1], 16, %2;\n"
                 :: "r"(dst), "l"(src), "r"(sz));
}

__global__ __launch_bounds__(256, 2)
void bf16_gemm(const __nv_bfloat16* __restrict__ Ah, const __nv_bfloat16* __restrict__ Al,
               const __nv_bfloat16* __restrict__ Bh, const __nv_bfloat16* __restrict__ Bl,
               const float* __restrict__ bias, void* __restrict__ Cv,
               int M, int N, int K, int halfOut)
{
    extern __shared__ uint8_t sm8[];
    uint32_t smb;
    asm("{ .reg .u64 t; cvta.to.shared.u64 t, %1; cvt.u32.u64 %0, t; }" : "=r"(smb) : "l"(sm8));

    const int m0 = blockIdx.y * BM;
    const int n0 = blockIdx.x * BN;
    const int tid = threadIdx.x;
    const int lane = tid & 31, warp = tid >> 5;
    const int wm = warp & 3, wn = warp >> 2;
    const int r = lane >> 2, cc = lane & 3;

    float acc[2][4][4];
    #pragma unroll
    for (int i = 0; i < 2; i++)
        #pragma unroll
        for (int j = 0; j < 4; j++)
            #pragma unroll
            for (int t = 0; t < 4; t++) acc[i][j][t] = 0.f;

    const int nst = K / BK;

    auto LOAD = [&](int s, int buf) {
        uint32_t base = smb + buf * STAGE_B;
        const int k0 = s * BK;
        #pragma unroll
        for (int half = 0; half < 2; half++) {
            int c = tid + half * 256;
            int row = c >> 2, col = c & 3;
            bool p = (m0 + row) < M;
            long g = (long)(p ? (m0 + row) : 0) * K + k0 + col * 8;
            uint32_t so = swz((uint32_t)(row * 64 + col * 16));
            cp16(base + so, Ah + g, p);
            cp16(base + A_TILE_B + so, Al + g, p);
        }
        {
            int row = tid >> 2, col = tid & 3;
            bool p = (n0 + row) < N;
            long g = (long)(p ? (n0 + row) : 0) * K + k0 + col * 8;
            uint32_t so = swz((uint32_t)(row * 64 + col * 16));
            cp16(base + 2 * A_TILE_B + so, Bh + g, p);
            cp16(base + 2 * A_TILE_B + B_TILE_B + so, Bl + g, p);
        }
        asm volatile("cp.async.commit_group;\n" ::: "memory");
    };

    auto COMPUTE = [&](int buf) {
        uint32_t base = smb + buf * STAGE_B;
        #pragma unroll
        for (int kk = 0; kk < 2; kk++) {
            uint32_t ah[2][4], al[2][4], bh[2][4], bl[2][4];
            #pragma unroll
            for (int mt = 0; mt < 2; mt++) {
                int row = wm * 32 + mt * 16 + (lane & 15);
                uint32_t off = swz((uint32_t)(row * 64 + (kk * 2 + (lane >> 4)) * 16));
                ldsm4(ah[mt], base + off);
                ldsm4(al[mt], base + A_TILE_B + off);
            }
            #pragma unroll
            for (int nt2 = 0; nt2 < 2; nt2++) {
                int row = wn * 32 + nt2 * 16 + (lane & 15);
                uint32_t off = swz((uint32_t)(row * 64 + (kk * 2 + (lane >> 4)) * 16));
                ldsm4(bh[nt2], base + 2 * A_TILE_B + off);
                ldsm4(bl[nt2], base + 2 * A_TILE_B + B_TILE_B + off);
            }
            #pragma unroll
            for (int mt = 0; mt < 2; mt++)
                #pragma unroll
                for (int nt = 0; nt < 4; nt++) {
                    int n2 = nt >> 1, hv = nt & 1;
                    MMA16816(acc[mt][nt], ah[mt], bh[n2][hv], bh[n2][hv + 2]);
                    MMA16816(acc[mt][nt], al[mt], bh[n2][hv], bh[n2][hv + 2]);
                    MMA16816(acc[mt][nt], ah[mt], bl[n2][hv], bl[n2][hv + 2]);
                }
        }
    };

    LOAD(0, 0);
    if (nst > 1) LOAD(1, 1);
    for (int s = 0; s < nst; s++) {
        if (s + 1 < nst) { asm volatile("cp.async.wait_group 1;\n" ::: "memory"); }
        else             { asm volatile("cp.async.wait_group 0;\n" ::: "memory"); }
        __syncthreads();
        if (s + 2 < nst) LOAD(s + 2, (s + 2) % NSTAGE);
        COMPUTE(s % NSTAGE);
    }

    // epilogue
    if (halfOut) {
        __half* C = (__half*)Cv;
        #pragma unroll
        for (int mt = 0; mt < 2; mt++) {
            int m = m0 + wm * 32 + mt * 16 + r;
            #pragma unroll
            for (int nt = 0; nt < 4; nt++) {
                int n = n0 + wn * 32 + nt * 8 + cc * 2;
                const float* d = acc[mt][nt];
                if (n + 1 < N) {
                    float b0 = bias[n], b1 = bias[n + 1];
                    if (m < M)
                        *(__half2*)&C[(long)m * N + n] = __floats2half2_rn(d[0] + b0, d[1] + b1);
                    if (m + 8 < M)
                        *(__half2*)&C[(long)(m + 8) * N + n] = __floats2half2_rn(d[2] + b0, d[3] + b1);
                } else if (n < N) {
                    float b0 = bias[n];
                    if (m < M)     C[(long)m * N + n]       = __float2half_rn(d[0] + b0);
                    if (m + 8 < M) C[(long)(m + 8) * N + n] = __float2half_rn(d[2] + b0);
                }
            }
        }
    } else {
        float* C = (float*)Cv;
        #pragma unroll
        for (int mt = 0; mt < 2; mt++) {
            int m = m0 + wm * 32 + mt * 16 + r;
            #pragma unroll
            for (int nt = 0; nt < 4; nt++) {
                int n = n0 + wn * 32 + nt * 8 + cc * 2;
                const float* d = acc[mt][nt];
                if (m < M) {
                    if (n < N)     C[(long)m * N + n]     = d[0] + bias[n];
                    if (n + 1 < N) C[(long)m * N + n + 1] = d[1] + bias[n + 1];
                }
                if (m + 8 < M) {
                    if (n < N)     C[(long)(m + 8) * N + n]     = d[2] + bias[n];
                    if (n + 1 < N) C[(long)(m + 8) * N + n + 1] = d[3] + bias[n + 1];
                }
            }
        }
    }
}

// ---------------- sampler: half2-vectorized gathers, 192 threads (1 warp/head) ----------------
__global__ __launch_bounds__(192)
void sample_kernel(const float* __restrict__ coor,
                   const float* __restrict__ cam2img,
                   const float* __restrict__ lidar2cam)
{
    const int q = blockIdx.x;
    const int b = blockIdx.y;
    const int tid = threadIdx.x;
    const int h = tid >> 5;        // head = warp
    const int d2 = tid & 31;       // half2 channel pair

    __shared__ float s_uv[2];
    __shared__ float s_logit[NH_][NL_*NP_];
    __shared__ float s_w[NH_][NL_*NP_];
    __shared__ int   s_idx[NH_][NL_*NP_][4];
    __shared__ float s_bw[NH_][NL_*NP_][4];

    if (tid == 0) {
        const float* L  = lidar2cam + b * 16;
        const float* Kc = cam2img + b * 16;
        float p0 = coor[((long)b * NQ_ + q) * 3 + 0];
        float p1 = coor[((long)b * NQ_ + q) * 3 + 1];
        float p2 = coor[((long)b * NQ_ + q) * 3 + 2];
        float pc[3], pr[3];
        #pragma unroll
        for (int i = 0; i < 3; i++)
            pc[i] = L[i*4+0]*p0 + L[i*4+1]*p1 + L[i*4+2]*p2 + L[i*4+3];
        #pragma unroll
        for (int i = 0; i < 3; i++)
            pr[i] = Kc[i*4+0]*pc[0] + Kc[i*4+1]*pc[1] + Kc[i*4+2]*pc[2] + Kc[i*4+3];
        s_uv[0] = pr[0] / pr[2];
        s_uv[1] = pr[1] / pr[2];
    }
    __syncthreads();

    const long bq = (long)b * NQ_ + q;
    const float* oa = g_oa + bq * NOA_;

    if (tid < NATT_) {
        const int hh = tid / (NL_*NP_);
        const int j  = tid - hh * (NL_*NP_);
        const int l = j / NP_;
        const int p = j - l * NP_;

        s_logit[hh][j] = oa[NOFF_ + hh * (NL_*NP_) + j];

        const float* offp = &oa[hh * (NL_*NP_*2) + l * (NP_*2) + p * 2];
        float px = s_uv[0] * c_SX[l] + offp[0] - 0.5f;
        float py = s_uv[1] * c_SY[l] + offp[1] - 0.5f;
        float x0 = floorf(px), y0 = floorf(py);
        float fx = px - x0, fy = py - y0;
        const int wl = c_W[l], hl = c_H[l];
        const int base_l = b * TOTHW_ + c_OFF[l];

        #pragma unroll
        for (int c = 0; c < 4; c++) {
            int dx = c & 1, dy = c >> 1;
            float xi = x0 + dx, yi = y0 + dy;
            bool valid = (xi >= 0.f) && (xi < (float)wl) && (yi >= 0.f) && (yi < (float)hl);
            float wgt = (dx ? fx : 1.f - fx) * (dy ? fy : 1.f - fy);
            float xc = fminf(fmaxf(xi, 0.f), (float)(wl - 1));
            float yc = fminf(fmaxf(yi, 0.f), (float)(hl - 1));
            int pix = (int)yc * wl + (int)xc;
            s_idx[hh][j][c] = (base_l + pix) * NHD_ + hh * DH_;
            s_bw[hh][j][c]  = valid ? wgt : 0.f;
        }
    }
    __syncthreads();

    if (tid < NATT_) {
        const int hh = tid / (NL_*NP_);
        const int j  = tid - hh * (NL_*NP_);
        float mx = -1e30f;
        #pragma unroll
        for (int jj = 0; jj < NL_*NP_; jj++) mx = fmaxf(mx, s_logit[hh][jj]);
        s_w[hh][j] = expf(s_logit[hh][j] - mx);
    }
    __syncthreads();

    float sum = 0.f;
    #pragma unroll
    for (int jj = 0; jj < NL_*NP_; jj++) sum += s_w[h][jj];
    const float rsum = 1.f / sum;

    float accx = 0.f, accy = 0.f;
    #pragma unroll 3
    for (int j = 0; j < NL_*NP_; j++) {
        float aw = s_w[h][j] * rsum;
        const int*   id = s_idx[h][j];
        const float* bw = s_bw[h][j];
        float2 v0 = __half22float2(*(reinterpret_cast<const __half2*>(g_vh16 + id[0]) + d2));
        float2 v1 = __half22float2(*(reinterpret_cast<const __half2*>(g_vh16 + id[1]) + d2));
        float2 v2 = __half22float2(*(reinterpret_cast<const __half2*>(g_vh16 + id[2]) + d2));
        float2 v3 = __half22float2(*(reinterpret_cast<const __half2*>(g_vh16 + id[3]) + d2));
        float sx = bw[0]*v0.x + bw[1]*v1.x + bw[2]*v2.x + bw[3]*v3.x;
        float sy = bw[0]*v0.y + bw[1]*v1.y + bw[2]*v2.y + bw[3]*v3.y;
        accx += aw * sx;
        accy += aw * sy;
    }
    long oidx = bq * NHD_ + h * DH_ + 2 * d2;
    __nv_bfloat16 hx = __float2bfloat16_rn(accx);
    __nv_bfloat16 hy = __float2bfloat16_rn(accy);
    __nv_bfloat162 H; H.x = hx; H.y = hy;
    __nv_bfloat162 L;
    L.x = __float2bfloat16_rn(accx - __bfloat162float(hx));
    L.y = __float2bfloat16_rn(accy - __bfloat162float(hy));
    *reinterpret_cast<__nv_bfloat162*>(&g_midh[oidx]) = H;
    *reinterpret_cast<__nv_bfloat162*>(&g_midl[oidx]) = L;
}

// ---------------- host launcher ----------------
extern "C" void kernel_launch(void* const* d_in, const int* in_sizes, int n_in,
                              void* d_out, int out_size)
{
    const float* x         = (const float*)d_in[0];
    const float* pe        = (const float*)d_in[1];
    const float* coor      = (const float*)d_in[2];
    const float* cam2img   = (const float*)d_in[3];
    const float* lidar2cam = (const float*)d_in[4];
    const float* feat0     = (const float*)d_in[5];
    const float* feat1     = (const float*)d_in[6];
    const float* feat2     = (const float*)d_in[7];
    const float* W_value   = (const float*)d_in[8];
    const float* b_value   = (const float*)d_in[9];
    const float* W_off     = (const float*)d_in[10];
    const float* b_off     = (const float*)d_in[11];
    const float* W_attn    = (const float*)d_in[12];
    const float* b_attn    = (const float*)d_in[13];
    const float* W_out     = (const float*)d_in[14];
    const float* b_out     = (const float*)d_in[15];
    float* out = (float*)d_out;

    float *poa, *pboa;
    __half* pv16;
    __nv_bfloat16 *pqh, *pql, *pfh, *pfl, *pmidh, *pmidl, *pwh, *pwl;
    cudaGetSymbolAddress((void**)&pv16, g_vh16);
    cudaGetSymbolAddress((void**)&poa, g_oa);
    cudaGetSymbolAddress((void**)&pboa, g_boa);
    cudaGetSymbolAddress((void**)&pqh, g_qh);
    cudaGetSymbolAddress((void**)&pql, g_ql);
    cudaGetSymbolAddress((void**)&pfh, g_fh);
    cudaGetSymbolAddress((void**)&pfl, g_fl);
    cudaGetSymbolAddress((void**)&pmidh, g_midh);
    cudaGetSymbolAddress((void**)&pmidl, g_midl);
    cudaGetSymbolAddress((void**)&pwh, g_wh);
    cudaGetSymbolAddress((void**)&pwl, g_wl);

    static bool attrSet = false;
    if (!attrSet) {
        cudaFuncSetAttribute(bf16_gemm, cudaFuncAttributeMaxDynamicSharedMemorySize, GEMM_SMEM);
        attrSet = true;
    }

    const int hw[3]  = {7680, 1920, 480};
    const int off[3] = {0, 7680, 9600};
    const float* feats[3] = {feat0, feat1, feat2};

    // 1: q = x + pe, split
    {
        int n4 = B_ * NQ_ * DM_ / 4;
        add_split_kernel<<<(n4 + 255) / 256, 256>>>(x, pe, pqh, pql, n4);
    }
    // 2-4: feature transpose+split
    for (int l = 0; l < 3; l++) {
        dim3 grid((hw[l] + 31) / 32, DM_ / 32, B_);
        transpose_split_kernel<<<grid, 256>>>(feats[l],
            pfh + (long)off[l] * DM_, pfl + (long)off[l] * DM_,
            DM_, hw[l], (long)DM_ * hw[l], (long)TOTHW_ * DM_);
    }
    // 5: all weight transposes + bias concat (one launch)
    {
        dim3 grid(12, 12, 5);
        prep_weights_kernel<<<grid, 256>>>(W_value, W_off, W_attn, W_out, b_off, b_attn);
    }
    // 6: value projection GEMM (fp16 out)  <- ncu -s 5 lands here
    {
        dim3 grid(NHD_ / BN, (B_ * TOTHW_ + BM - 1) / BM);
        bf16_gemm<<<grid, 256, GEMM_SMEM>>>(pfh, pfl, pwh + WV_OFF, pwl + WV_OFF,
                                            b_value, pv16, B_ * TOTHW_, NHD_, DM_, 1);
    }
    // 7: combined offsets+attn GEMM
    {
        dim3 grid((NOA_ + BN - 1) / BN, (B_ * NQ_) / BM);
        bf16_gemm<<<grid, 256, GEMM_SMEM>>>(pqh, pql, pwh + WOA_OFF, pwl + WOA_OFF,
                                            pboa, poa, B_ * NQ_, NOA_, DM_, 0);
    }
    // 8: sampler
    {
        dim3 grid(NQ_, B_);
        sample_kernel<<<grid, 192>>>(coor, cam2img, lidar2cam);
    }
    // 9: output GEMM
    {
        dim3 grid(DM_ / BN, (B_ * NQ_) / BM);
        bf16_gemm<<<grid, 256, GEMM_SMEM>>>(pmidh, pmidl, pwh + WOUT_OFF, pwl + WOUT_OFF,
                                            b_out, out, B_ * NQ_, DM_, NHD_, 0);
    }
}

// round 9
// speedup vs baseline: 1.5298x; 1.0987x over previous
#include <cuda_runtime.h>
#include <cuda_bf16.h>
#include <cuda_fp16.h>
#include <math.h>
#include <stdint.h>

// ---------------- problem constants ----------------
#define B_   2
#define NQ_  8192
#define DM_  256
#define NH_  6
#define DH_  64
#define NL_  3
#define NP_  9
#define NHD_ (NH_*DH_)            // 384
#define NOFF_ (NH_*NL_*NP_*2)     // 324
#define NATT_ (NH_*NL_*NP_)       // 162
#define NOA_  (NOFF_ + NATT_)     // 486
#define TOTHW_ 10080              // 7680+1920+480

// level tables
__device__ __constant__ int   c_W[3]   = {160, 80, 40};
__device__ __constant__ int   c_H[3]   = {48, 24, 12};
__device__ __constant__ int   c_OFF[3] = {0, 7680, 9600};
__device__ __constant__ float c_SX[3]  = {160.f/1280.f, 80.f/1280.f, 40.f/1280.f};
__device__ __constant__ float c_SY[3]  = {48.f/384.f, 24.f/384.f, 12.f/384.f};

// ---------------- scratch (no allocs allowed) ----------------
__device__ __half g_vh16[(size_t)B_ * TOTHW_ * NHD_];
__device__ float g_oa  [(size_t)B_ * NQ_ * NOA_];
__device__ float g_boa [NOA_];

__device__ __nv_bfloat16 g_qh [(size_t)B_ * NQ_ * DM_];
__device__ __nv_bfloat16 g_ql [(size_t)B_ * NQ_ * DM_];
__device__ __nv_bfloat16 g_fh [(size_t)B_ * TOTHW_ * DM_];
__device__ __nv_bfloat16 g_fl [(size_t)B_ * TOTHW_ * DM_];
__device__ __nv_bfloat16 g_midh[(size_t)B_ * NQ_ * NHD_];
__device__ __nv_bfloat16 g_midl[(size_t)B_ * NQ_ * NHD_];

#define WV_OFF   0
#define WOA_OFF  (384*256)
#define WOUT_OFF (WOA_OFF + NOA_*256)
#define WTOT_    (WOUT_OFF + 256*384)
__device__ __nv_bfloat16 g_wh[WTOT_];
__device__ __nv_bfloat16 g_wl[WTOT_];

// ================= prep kernels =================
__global__ __launch_bounds__(256)
void add_split_kernel(const float* __restrict__ x, const float* __restrict__ pe,
                      __nv_bfloat16* __restrict__ oh, __nv_bfloat16* __restrict__ ol, int n4)
{
    int i = blockIdx.x * blockDim.x + threadIdx.x;
    if (i >= n4) return;
    float4 a = reinterpret_cast<const float4*>(x)[i];
    float4 b = reinterpret_cast<const float4*>(pe)[i];
    float v[4] = {a.x + b.x, a.y + b.y, a.z + b.z, a.w + b.w};
    __nv_bfloat16 h[4], l[4];
    #pragma unroll
    for (int j = 0; j < 4; j++) {
        h[j] = __float2bfloat16_rn(v[j]);
        l[j] = __float2bfloat16_rn(v[j] - __bfloat162float(h[j]));
    }
    *reinterpret_cast<uint2*>(oh + (size_t)i*4) = *reinterpret_cast<uint2*>(h);
    *reinterpret_cast<uint2*>(ol + (size_t)i*4) = *reinterpret_cast<uint2*>(l);
}

// fused feature transpose+split: all 3 levels, both batches, one launch.
// in feat[l]: [B][256][hw_l] -> planes [b][OFF_l + pix][256]
__global__ __launch_bounds__(256)
void feat_transpose_kernel(const float* __restrict__ f0, const float* __restrict__ f1,
                           const float* __restrict__ f2)
{
    __shared__ float t[32][33];
    const int b = blockIdx.z;
    int xt = blockIdx.x;
    int l, c0;
    const float* in;
    int hwl;
    if (xt < 240)      { l = 0; c0 = xt * 32;         in = f0; hwl = 7680; }
    else if (xt < 300) { l = 1; c0 = (xt - 240) * 32; in = f1; hwl = 1920; }
    else               { l = 2; c0 = (xt - 300) * 32; in = f2; hwl = 480;  }
    in += (long)b * DM_ * hwl;
    const int r0 = blockIdx.y * 32;
    const int tx = threadIdx.x & 31, ty = threadIdx.x >> 5;

    #pragma unroll
    for (int i = 0; i < 32; i += 8)
        t[ty + i][tx] = in[(long)(r0 + ty + i) * hwl + c0 + tx];
    __syncthreads();
    const long outBase = ((long)b * TOTHW_ + c_OFF[l] + c0) * DM_ + r0;
    #pragma unroll
    for (int i = 0; i < 32; i += 8) {
        float v = t[tx][ty + i];
        __nv_bfloat16 h = __float2bfloat16_rn(v);
        long o = outBase + (long)(ty + i) * DM_ + tx;
        g_fh[o] = h;
        g_fl[o] = __float2bfloat16_rn(v - __bfloat162float(h));
    }
}

// fused: weight transposes (+split) and bias concat
__global__ __launch_bounds__(256)
void prep_weights_kernel(const float* __restrict__ Wv, const float* __restrict__ Woff,
                         const float* __restrict__ Wattn, const float* __restrict__ Wout,
                         const float* __restrict__ boff, const float* __restrict__ battn)
{
    const int z = blockIdx.z;
    if (z == 4) {
        if (blockIdx.y != 0 || blockIdx.x > 1) return;
        int i = blockIdx.x * 256 + threadIdx.x;
        if (i < NOFF_) g_boa[i] = boff[i];
        else if (i < NOA_) g_boa[i] = battn[i - NOFF_];
        return;
    }
    int R, C; const float* in; long base; int rowOff = 0;
    if (z == 0)      { in = Wv;    R = 256; C = 384; base = WV_OFF; }
    else if (z == 1) { in = Woff;  R = 256; C = 324; base = WOA_OFF; }
    else if (z == 2) { in = Wattn; R = 256; C = 162; base = WOA_OFF; rowOff = 324; }
    else             { in = Wout;  R = 384; C = 256; base = WOUT_OFF; }

    const int c0 = blockIdx.x * 32, r0 = blockIdx.y * 32;
    if (c0 >= C || r0 >= R) return;

    __shared__ float t[32][33];
    const int tx = threadIdx.x & 31, ty = threadIdx.x >> 5;
    #pragma unroll
    for (int i = 0; i < 32; i += 8) {
        int r = r0 + ty + i, c = c0 + tx;
        t[ty + i][tx] = (r < R && c < C) ? in[(long)r * C + c] : 0.f;
    }
    __syncthreads();
    #pragma unroll
    for (int i = 0; i < 32; i += 8) {
        int c = c0 + ty + i, r = r0 + tx;
        if (c < C && r < R) {
            float v = t[tx][ty + i];
            __nv_bfloat16 h = __float2bfloat16_rn(v);
            long o = base + (long)(rowOff + c) * R + r;
            g_wh[o] = h;
            g_wl[o] = __float2bfloat16_rn(v - __bfloat162float(h));
        }
    }
}

// ================= bf16 tensor-core GEMM (3-stage cp.async pipeline) =================
#define BM 128
#define BN 64
#define BK 32
#define A_TILE_B (BM*BK*2)
#define B_TILE_B (BN*BK*2)
#define STAGE_B  (2*A_TILE_B + 2*B_TILE_B)
#define NSTAGE 3
#define GEMM_SMEM (NSTAGE*STAGE_B)

#define MMA16816(d, a, b0v, b1v) \
  asm volatile("mma.sync.aligned.m16n8k16.row.col.f32.bf16.bf16.f32 " \
    "{%0,%1,%2,%3},{%4,%5,%6,%7},{%8,%9},{%0,%1,%2,%3};" \
    : "+f"((d)[0]), "+f"((d)[1]), "+f"((d)[2]), "+f"((d)[3]) \
    : "r"((a)[0]), "r"((a)[1]), "r"((a)[2]), "r"((a)[3]), "r"(b0v), "r"(b1v))

__device__ __forceinline__ uint32_t swz(uint32_t off) {
    return off ^ ((off >> 3) & 0x30);
}
__device__ __forceinline__ void ldsm4(uint32_t (&r)[4], uint32_t addr) {
    asm volatile("ldmatrix.sync.aligned.m8n8.x4.shared.b16 {%0,%1,%2,%3}, [%4];"
        : "=r"(r[0]), "=r"(r[1]), "=r"(r[2]), "=r"(r[3]) : "r"(addr));
}
__device__ __forceinline__ void cp16(uint32_t dst, const void* src, bool pred) {
    int sz = pred ? 16 : 0;
    asm volatile("cp.async.cg.shared.global [%0], [%1], 16, %2;\n"
                 :: "r"(dst), "l"(src), "r"(sz));
}

__global__ __launch_bounds__(256, 2)
void bf16_gemm(const __nv_bfloat16* __restrict__ Ah, const __nv_bfloat16* __restrict__ Al,
               const __nv_bfloat16* __restrict__ Bh, const __nv_bfloat16* __restrict__ Bl,
               const float* __restrict__ bias, void* __restrict__ Cv,
               int M, int N, int K, int halfOut)
{
    extern __shared__ uint8_t sm8[];
    uint32_t smb;
    asm("{ .reg .u64 t; cvta.to.shared.u64 t, %1; cvt.u32.u64 %0, t; }" : "=r"(smb) : "l"(sm8));

    const int m0 = blockIdx.y * BM;
    const int n0 = blockIdx.x * BN;
    const int tid = threadIdx.x;
    const int lane = tid & 31, warp = tid >> 5;
    const int wm = warp & 3, wn = warp >> 2;
    const int r = lane >> 2, cc = lane & 3;

    float acc[2][4][4];
    #pragma unroll
    for (int i = 0; i < 2; i++)
        #pragma unroll
        for (int j = 0; j < 4; j++)
            #pragma unroll
            for (int t = 0; t < 4; t++) acc[i][j][t] = 0.f;

    const int nst = K / BK;

    auto LOAD = [&](int s, int buf) {
        uint32_t base = smb + buf * STAGE_B;
        const int k0 = s * BK;
        #pragma unroll
        for (int half = 0; half < 2; half++) {
            int c = tid + half * 256;
            int row = c >> 2, col = c & 3;
            bool p = (m0 + row) < M;
            long g = (long)(p ? (m0 + row) : 0) * K + k0 + col * 8;
            uint32_t so = swz((uint32_t)(row * 64 + col * 16));
            cp16(base + so, Ah + g, p);
            cp16(base + A_TILE_B + so, Al + g, p);
        }
        {
            int row = tid >> 2, col = tid & 3;
            bool p = (n0 + row) < N;
            long g = (long)(p ? (n0 + row) : 0) * K + k0 + col * 8;
            uint32_t so = swz((uint32_t)(row * 64 + col * 16));
            cp16(base + 2 * A_TILE_B + so, Bh + g, p);
            cp16(base + 2 * A_TILE_B + B_TILE_B + so, Bl + g, p);
        }
        asm volatile("cp.async.commit_group;\n" ::: "memory");
    };

    auto COMPUTE = [&](int buf) {
        uint32_t base = smb + buf * STAGE_B;
        #pragma unroll
        for (int kk = 0; kk < 2; kk++) {
            uint32_t ah[2][4], al[2][4], bh[2][4], bl[2][4];
            #pragma unroll
            for (int mt = 0; mt < 2; mt++) {
                int row = wm * 32 + mt * 16 + (lane & 15);
                uint32_t off = swz((uint32_t)(row * 64 + (kk * 2 + (lane >> 4)) * 16));
                ldsm4(ah[mt], base + off);
                ldsm4(al[mt], base + A_TILE_B + off);
            }
            #pragma unroll
            for (int nt2 = 0; nt2 < 2; nt2++) {
                int row = wn * 32 + nt2 * 16 + (lane & 15);
                uint32_t off = swz((uint32_t)(row * 64 + (kk * 2 + (lane >> 4)) * 16));
                ldsm4(bh[nt2], base + 2 * A_TILE_B + off);
                ldsm4(bl[nt2], base + 2 * A_TILE_B + B_TILE_B + off);
            }
            #pragma unroll
            for (int mt = 0; mt < 2; mt++)
                #pragma unroll
                for (int nt = 0; nt < 4; nt++) {
                    int n2 = nt >> 1, hv = nt & 1;
                    MMA16816(acc[mt][nt], ah[mt], bh[n2][hv], bh[n2][hv + 2]);
                    MMA16816(acc[mt][nt], al[mt], bh[n2][hv], bh[n2][hv + 2]);
                    MMA16816(acc[mt][nt], ah[mt], bl[n2][hv], bl[n2][hv + 2]);
                }
        }
    };

    LOAD(0, 0);
    if (nst > 1) LOAD(1, 1);
    for (int s = 0; s < nst; s++) {
        if (s + 1 < nst) { asm volatile("cp.async.wait_group 1;\n" ::: "memory"); }
        else             { asm volatile("cp.async.wait_group 0;\n" ::: "memory"); }
        __syncthreads();
        if (s + 2 < nst) LOAD(s + 2, (s + 2) % NSTAGE);
        COMPUTE(s % NSTAGE);
    }

    if (halfOut) {
        __half* C = (__half*)Cv;
        #pragma unroll
        for (int mt = 0; mt < 2; mt++) {
            int m = m0 + wm * 32 + mt * 16 + r;
            #pragma unroll
            for (int nt = 0; nt < 4; nt++) {
                int n = n0 + wn * 32 + nt * 8 + cc * 2;
                const float* d = acc[mt][nt];
                if (n + 1 < N) {
                    float b0 = bias[n], b1 = bias[n + 1];
                    if (m < M)
                        *(__half2*)&C[(long)m * N + n] = __floats2half2_rn(d[0] + b0, d[1] + b1);
                    if (m + 8 < M)
                        *(__half2*)&C[(long)(m + 8) * N + n] = __floats2half2_rn(d[2] + b0, d[3] + b1);
                } else if (n < N) {
                    float b0 = bias[n];
                    if (m < M)     C[(long)m * N + n]       = __float2half_rn(d[0] + b0);
                    if (m + 8 < M) C[(long)(m + 8) * N + n] = __float2half_rn(d[2] + b0);
                }
            }
        }
    } else {
        float* C = (float*)Cv;
        #pragma unroll
        for (int mt = 0; mt < 2; mt++) {
            int m = m0 + wm * 32 + mt * 16 + r;
            #pragma unroll
            for (int nt = 0; nt < 4; nt++) {
                int n = n0 + wn * 32 + nt * 8 + cc * 2;
                const float* d = acc[mt][nt];
                if (m < M) {
                    if (n < N)     C[(long)m * N + n]     = d[0] + bias[n];
                    if (n + 1 < N) C[(long)m * N + n + 1] = d[1] + bias[n + 1];
                }
                if (m + 8 < M) {
                    if (n < N)     C[(long)(m + 8) * N + n]     = d[2] + bias[n];
                    if (n + 1 < N) C[(long)(m + 8) * N + n + 1] = d[3] + bias[n + 1];
                }
            }
        }
    }
}

// ---------------- sampler v3: 2 samples per warp iteration, uint2 gathers ----------------
// 192 threads: warp = head; lane half (16 lanes) handles one sample j of a pair,
// each lane loads 4 fp16 channels (uint2). Cross-half combine via shfl_xor(16).
__global__ __launch_bounds__(192)
void sample_kernel(const float* __restrict__ coor,
                   const float* __restrict__ cam2img,
                   const float* __restrict__ lidar2cam)
{
    const int q = blockIdx.x;
    const int b = blockIdx.y;
    const int tid = threadIdx.x;
    const int h    = tid >> 5;
    const int lane = tid & 31;
    const int half = lane >> 4;
    const int l16  = lane & 15;

    __shared__ float  s_uv[2];
    __shared__ float  s_logit[NH_][NL_*NP_];
    __shared__ float  s_w[NH_][28];
    __shared__ int4   s_idx[NH_][28];
    __shared__ float4 s_bw[NH_][28];

    if (tid == 0) {
        const float* L  = lidar2cam + b * 16;
        const float* Kc = cam2img + b * 16;
        float p0 = coor[((long)b * NQ_ + q) * 3 + 0];
        float p1 = coor[((long)b * NQ_ + q) * 3 + 1];
        float p2 = coor[((long)b * NQ_ + q) * 3 + 2];
        float pc[3], pr[3];
        #pragma unroll
        for (int i = 0; i < 3; i++)
            pc[i] = L[i*4+0]*p0 + L[i*4+1]*p1 + L[i*4+2]*p2 + L[i*4+3];
        #pragma unroll
        for (int i = 0; i < 3; i++)
            pr[i] = Kc[i*4+0]*pc[0] + Kc[i*4+1]*pc[1] + Kc[i*4+2]*pc[2] + Kc[i*4+3];
        s_uv[0] = pr[0] / pr[2];
        s_uv[1] = pr[1] / pr[2];
    }
    __syncthreads();

    const long bq = (long)b * NQ_ + q;
    const float* oa = g_oa + bq * NOA_;

    if (tid < NATT_) {
        const int hh = tid / (NL_*NP_);
        const int j  = tid - hh * (NL_*NP_);
        const int l = j / NP_;
        const int p = j - l * NP_;

        s_logit[hh][j] = oa[NOFF_ + hh * (NL_*NP_) + j];

        const float* offp = &oa[hh * (NL_*NP_*2) + l * (NP_*2) + p * 2];
        float px = s_uv[0] * c_SX[l] + offp[0] - 0.5f;
        float py = s_uv[1] * c_SY[l] + offp[1] - 0.5f;
        float x0 = floorf(px), y0 = floorf(py);
        float fx = px - x0, fy = py - y0;
        const int wl = c_W[l], hl = c_H[l];
        const int base_l = b * TOTHW_ + c_OFF[l];

        int   idv[4];
        float bwv[4];
        #pragma unroll
        for (int c = 0; c < 4; c++) {
            int dx = c & 1, dy = c >> 1;
            float xi = x0 + dx, yi = y0 + dy;
            bool valid = (xi >= 0.f) && (xi < (float)wl) && (yi >= 0.f) && (yi < (float)hl);
            float wgt = (dx ? fx : 1.f - fx) * (dy ? fy : 1.f - fy);
            float xc = fminf(fmaxf(xi, 0.f), (float)(wl - 1));
            float yc = fminf(fmaxf(yi, 0.f), (float)(hl - 1));
            int pix = (int)yc * wl + (int)xc;
            idv[c] = (base_l + pix) * NHD_ + hh * DH_;
            bwv[c] = valid ? wgt : 0.f;
        }
        s_idx[hh][j] = make_int4(idv[0], idv[1], idv[2], idv[3]);
        s_bw[hh][j]  = make_float4(bwv[0], bwv[1], bwv[2], bwv[3]);
    }
    __syncthreads();

    if (tid < NATT_) {
        const int hh = tid / (NL_*NP_);
        const int j  = tid - hh * (NL_*NP_);
        float mx = -1e30f;
        #pragma unroll
        for (int jj = 0; jj < NL_*NP_; jj++) mx = fmaxf(mx, s_logit[hh][jj]);
        s_w[hh][j] = expf(s_logit[hh][j] - mx);
    }
    if (tid < NH_) {
        // pad entry j=27: zero weight, safe (valid) addresses
        s_w[tid][27]  = 0.f;
        s_idx[tid][27] = s_idx[tid][26];
        s_bw[tid][27]  = make_float4(0.f, 0.f, 0.f, 0.f);
    }
    __syncthreads();

    float sum = 0.f;
    #pragma unroll
    for (int jj = 0; jj < NL_*NP_; jj++) sum += s_w[h][jj];
    const float rsum = 1.f / sum;

    float a0 = 0.f, a1 = 0.f, a2 = 0.f, a3 = 0.f;
    #pragma unroll
    for (int jp = 0; jp < 14; jp++) {
        const int j = jp * 2 + half;
        const float aw = s_w[h][j] * rsum;
        const int4   id = s_idx[h][j];
        const float4 bw = s_bw[h][j];
        float t0 = 0.f, t1 = 0.f, t2 = 0.f, t3 = 0.f;
        const int ids[4] = {id.x, id.y, id.z, id.w};
        const float bws[4] = {bw.x, bw.y, bw.z, bw.w};
        #pragma unroll
        for (int c = 0; c < 4; c++) {
            uint2 u = *reinterpret_cast<const uint2*>(g_vh16 + ids[c] + l16 * 4);
            __half2 ha = *reinterpret_cast<__half2*>(&u.x);
            __half2 hb = *reinterpret_cast<__half2*>(&u.y);
            float2 fa = __half22float2(ha);
            float2 fb = __half22float2(hb);
            float w = bws[c];
            t0 += w * fa.x; t1 += w * fa.y; t2 += w * fb.x; t3 += w * fb.y;
        }
        a0 += aw * t0; a1 += aw * t1; a2 += aw * t2; a3 += aw * t3;
    }
    // combine the two halves (j even + j odd)
    a0 += __shfl_xor_sync(0xffffffffu, a0, 16);
    a1 += __shfl_xor_sync(0xffffffffu, a1, 16);
    a2 += __shfl_xor_sync(0xffffffffu, a2, 16);
    a3 += __shfl_xor_sync(0xffffffffu, a3, 16);

    if (half == 0) {
        long oidx = bq * NHD_ + h * DH_ + l16 * 4;
        float av[4] = {a0, a1, a2, a3};
        __nv_bfloat16 hi[4], lo[4];
        #pragma unroll
        for (int i = 0; i < 4; i++) {
            hi[i] = __float2bfloat16_rn(av[i]);
            lo[i] = __float2bfloat16_rn(av[i] - __bfloat162float(hi[i]));
        }
        *reinterpret_cast<uint2*>(&g_midh[oidx]) = *reinterpret_cast<uint2*>(hi);
        *reinterpret_cast<uint2*>(&g_midl[oidx]) = *reinterpret_cast<uint2*>(lo);
    }
}

// ---------------- host launcher ----------------
extern "C" void kernel_launch(void* const* d_in, const int* in_sizes, int n_in,
                              void* d_out, int out_size)
{
    const float* x         = (const float*)d_in[0];
    const float* pe        = (const float*)d_in[1];
    const float* coor      = (const float*)d_in[2];
    const float* cam2img   = (const float*)d_in[3];
    const float* lidar2cam = (const float*)d_in[4];
    const float* feat0     = (const float*)d_in[5];
    const float* feat1     = (const float*)d_in[6];
    const float* feat2     = (const float*)d_in[7];
    const float* W_value   = (const float*)d_in[8];
    const float* b_value   = (const float*)d_in[9];
    const float* W_off     = (const float*)d_in[10];
    const float* b_off     = (const float*)d_in[11];
    const float* W_attn    = (const float*)d_in[12];
    const float* b_attn    = (const float*)d_in[13];
    const float* W_out     = (const float*)d_in[14];
    const float* b_out     = (const float*)d_in[15];
    float* out = (float*)d_out;

    float *poa, *pboa;
    __half* pv16;
    __nv_bfloat16 *pqh, *pql, *pfh, *pfl, *pmidh, *pmidl, *pwh, *pwl;
    cudaGetSymbolAddress((void**)&pv16, g_vh16);
    cudaGetSymbolAddress((void**)&poa, g_oa);
    cudaGetSymbolAddress((void**)&pboa, g_boa);
    cudaGetSymbolAddress((void**)&pqh, g_qh);
    cudaGetSymbolAddress((void**)&pql, g_ql);
    cudaGetSymbolAddress((void**)&pfh, g_fh);
    cudaGetSymbolAddress((void**)&pfl, g_fl);
    cudaGetSymbolAddress((void**)&pmidh, g_midh);
    cudaGetSymbolAddress((void**)&pmidl, g_midl);
    cudaGetSymbolAddress((void**)&pwh, g_wh);
    cudaGetSymbolAddress((void**)&pwl, g_wl);

    static bool attrSet = false;
    if (!attrSet) {
        cudaFuncSetAttribute(bf16_gemm, cudaFuncAttributeMaxDynamicSharedMemorySize, GEMM_SMEM);
        attrSet = true;
    }

    // 1: weight transposes + bias concat
    {
        dim3 grid(12, 12, 5);
        prep_weights_kernel<<<grid, 256>>>(W_value, W_off, W_attn, W_out, b_off, b_attn);
    }
    // 2: q = x + pe, split
    {
        int n4 = B_ * NQ_ * DM_ / 4;
        add_split_kernel<<<(n4 + 255) / 256, 256>>>(x, pe, pqh, pql, n4);
    }
    // 3: fused feature transpose+split (all levels, both batches)
    {
        dim3 grid(315, 8, B_);
        feat_transpose_kernel<<<grid, 256>>>(feat0, feat1, feat2);
    }
    // 4: value projection GEMM (fp16 out)
    {
        dim3 grid(NHD_ / BN, (B_ * TOTHW_ + BM - 1) / BM);
        bf16_gemm<<<grid, 256, GEMM_SMEM>>>(pfh, pfl, pwh + WV_OFF, pwl + WV_OFF,
                                            b_value, pv16, B_ * TOTHW_, NHD_, DM_, 1);
    }
    // 5: combined offsets+attn GEMM
    {
        dim3 grid((NOA_ + BN - 1) / BN, (B_ * NQ_) / BM);
        bf16_gemm<<<grid, 256, GEMM_SMEM>>>(pqh, pql, pwh + WOA_OFF, pwl + WOA_OFF,
                                            pboa, poa, B_ * NQ_, NOA_, DM_, 0);
    }
    // 6: sampler
    {
        dim3 grid(NQ_, B_);
        sample_kernel<<<grid, 192>>>(coor, cam2img, lidar2cam);
    }
    // 7: output GEMM
    {
        dim3 grid(DM_ / BN, (B_ * NQ_) / BM);
        bf16_gemm<<<grid, 256, GEMM_SMEM>>>(pmidh, pmidl, pwh + WOUT_OFF, pwl + WOUT_OFF,
                                            b_out, out, B_ * NQ_, DM_, NHD_, 0);
    }
}

// round 10
// speedup vs baseline: 1.5554x; 1.0167x over previous
#include <cuda_runtime.h>
#include <cuda_bf16.h>
#include <cuda_fp16.h>
#include <math.h>
#include <stdint.h>

// ---------------- problem constants ----------------
#define B_   2
#define NQ_  8192
#define DM_  256
#define NH_  6
#define DH_  64
#define NL_  3
#define NP_  9
#define NHD_ (NH_*DH_)            // 384
#define NOFF_ (NH_*NL_*NP_*2)     // 324
#define NATT_ (NH_*NL_*NP_)       // 162
#define NOA_  (NOFF_ + NATT_)     // 486
#define TOTHW_ 10080              // 7680+1920+480

// level tables
__device__ __constant__ int   c_W[3]   = {160, 80, 40};
__device__ __constant__ int   c_H[3]   = {48, 24, 12};
__device__ __constant__ int   c_OFF[3] = {0, 7680, 9600};
__device__ __constant__ float c_SX[3]  = {160.f/1280.f, 80.f/1280.f, 40.f/1280.f};
__device__ __constant__ float c_SY[3]  = {48.f/384.f, 24.f/384.f, 12.f/384.f};

// ---------------- scratch (no allocs allowed) ----------------
__device__ __half g_vh16[(size_t)B_ * TOTHW_ * NHD_];
__device__ float g_oa  [(size_t)B_ * NQ_ * NOA_];
__device__ float g_boa [NOA_];

__device__ __nv_bfloat16 g_qh [(size_t)B_ * NQ_ * DM_];
__device__ __nv_bfloat16 g_ql [(size_t)B_ * NQ_ * DM_];
__device__ __nv_bfloat16 g_fh [(size_t)B_ * TOTHW_ * DM_];
__device__ __nv_bfloat16 g_fl [(size_t)B_ * TOTHW_ * DM_];
__device__ __nv_bfloat16 g_midh[(size_t)B_ * NQ_ * NHD_];
__device__ __nv_bfloat16 g_midl[(size_t)B_ * NQ_ * NHD_];

#define WV_OFF   0
#define WOA_OFF  (384*256)
#define WOUT_OFF (WOA_OFF + NOA_*256)
#define WTOT_    (WOUT_OFF + 256*384)
__device__ __nv_bfloat16 g_wh[WTOT_];
__device__ __nv_bfloat16 g_wl[WTOT_];

// ================= prep kernels =================
__global__ __launch_bounds__(256)
void add_split_kernel(const float* __restrict__ x, const float* __restrict__ pe,
                      __nv_bfloat16* __restrict__ oh, __nv_bfloat16* __restrict__ ol, int n4)
{
    int i = blockIdx.x * blockDim.x + threadIdx.x;
    if (i >= n4) return;
    float4 a = reinterpret_cast<const float4*>(x)[i];
    float4 b = reinterpret_cast<const float4*>(pe)[i];
    float v[4] = {a.x + b.x, a.y + b.y, a.z + b.z, a.w + b.w};
    __nv_bfloat16 h[4], l[4];
    #pragma unroll
    for (int j = 0; j < 4; j++) {
        h[j] = __float2bfloat16_rn(v[j]);
        l[j] = __float2bfloat16_rn(v[j] - __bfloat162float(h[j]));
    }
    *reinterpret_cast<uint2*>(oh + (size_t)i*4) = *reinterpret_cast<uint2*>(h);
    *reinterpret_cast<uint2*>(ol + (size_t)i*4) = *reinterpret_cast<uint2*>(l);
}

// fused feature transpose+split: all 3 levels, both batches, one launch.
__global__ __launch_bounds__(256)
void feat_transpose_kernel(const float* __restrict__ f0, const float* __restrict__ f1,
                           const float* __restrict__ f2)
{
    __shared__ float t[32][33];
    const int b = blockIdx.z;
    int xt = blockIdx.x;
    int l, c0;
    const float* in;
    int hwl;
    if (xt < 240)      { l = 0; c0 = xt * 32;         in = f0; hwl = 7680; }
    else if (xt < 300) { l = 1; c0 = (xt - 240) * 32; in = f1; hwl = 1920; }
    else               { l = 2; c0 = (xt - 300) * 32; in = f2; hwl = 480;  }
    in += (long)b * DM_ * hwl;
    const int r0 = blockIdx.y * 32;
    const int tx = threadIdx.x & 31, ty = threadIdx.x >> 5;

    #pragma unroll
    for (int i = 0; i < 32; i += 8)
        t[ty + i][tx] = in[(long)(r0 + ty + i) * hwl + c0 + tx];
    __syncthreads();
    const long outBase = ((long)b * TOTHW_ + c_OFF[l] + c0) * DM_ + r0;
    #pragma unroll
    for (int i = 0; i < 32; i += 8) {
        float v = t[tx][ty + i];
        __nv_bfloat16 h = __float2bfloat16_rn(v);
        long o = outBase + (long)(ty + i) * DM_ + tx;
        g_fh[o] = h;
        g_fl[o] = __float2bfloat16_rn(v - __bfloat162float(h));
    }
}

// fused: weight transposes (+split) and bias concat
__global__ __launch_bounds__(256)
void prep_weights_kernel(const float* __restrict__ Wv, const float* __restrict__ Woff,
                         const float* __restrict__ Wattn, const float* __restrict__ Wout,
                         const float* __restrict__ boff, const float* __restrict__ battn)
{
    const int z = blockIdx.z;
    if (z == 4) {
        if (blockIdx.y != 0 || blockIdx.x > 1) return;
        int i = blockIdx.x * 256 + threadIdx.x;
        if (i < NOFF_) g_boa[i] = boff[i];
        else if (i < NOA_) g_boa[i] = battn[i - NOFF_];
        return;
    }
    int R, C; const float* in; long base; int rowOff = 0;
    if (z == 0)      { in = Wv;    R = 256; C = 384; base = WV_OFF; }
    else if (z == 1) { in = Woff;  R = 256; C = 324; base = WOA_OFF; }
    else if (z == 2) { in = Wattn; R = 256; C = 162; base = WOA_OFF; rowOff = 324; }
    else             { in = Wout;  R = 384; C = 256; base = WOUT_OFF; }

    const int c0 = blockIdx.x * 32, r0 = blockIdx.y * 32;
    if (c0 >= C || r0 >= R) return;

    __shared__ float t[32][33];
    const int tx = threadIdx.x & 31, ty = threadIdx.x >> 5;
    #pragma unroll
    for (int i = 0; i < 32; i += 8) {
        int r = r0 + ty + i, c = c0 + tx;
        t[ty + i][tx] = (r < R && c < C) ? in[(long)r * C + c] : 0.f;
    }
    __syncthreads();
    #pragma unroll
    for (int i = 0; i < 32; i += 8) {
        int c = c0 + ty + i, r = r0 + tx;
        if (c < C && r < R) {
            float v = t[tx][ty + i];
            __nv_bfloat16 h = __float2bfloat16_rn(v);
            long o = base + (long)(rowOff + c) * R + r;
            g_wh[o] = h;
            g_wl[o] = __float2bfloat16_rn(v - __bfloat162float(h));
        }
    }
}

// ================= bf16 tensor-core GEMM =================
// 128 threads, 4 warps, warp tile 32x64, BM=128 BN=64 BK=32, 3-stage cp.async
#define BM 128
#define BN 64
#define BK 32
#define A_TILE_B (BM*BK*2)
#define B_TILE_B (BN*BK*2)
#define STAGE_B  (2*A_TILE_B + 2*B_TILE_B)   // 24576
#define NSTAGE 3
#define GEMM_SMEM (NSTAGE*STAGE_B)           // 73728

#define MMA16816(d, a, b0v, b1v) \
  asm volatile("mma.sync.aligned.m16n8k16.row.col.f32.bf16.bf16.f32 " \
    "{%0,%1,%2,%3},{%4,%5,%6,%7},{%8,%9},{%0,%1,%2,%3};" \
    : "+f"((d)[0]), "+f"((d)[1]), "+f"((d)[2]), "+f"((d)[3]) \
    : "r"((a)[0]), "r"((a)[1]), "r"((a)[2]), "r"((a)[3]), "r"(b0v), "r"(b1v))

__device__ __forceinline__ uint32_t swz(uint32_t off) {
    return off ^ ((off >> 3) & 0x30);
}
__device__ __forceinline__ void ldsm4(uint32_t (&r)[4], uint32_t addr) {
    asm volatile("ldmatrix.sync.aligned.m8n8.x4.shared.b16 {%0,%1,%2,%3}, [%4];"
        : "=r"(r[0]), "=r"(r[1]), "=r"(r[2]), "=r"(r[3]) : "r"(addr));
}
__device__ __forceinline__ void cp16(uint32_t dst, const void* src, bool pred) {
    int sz = pred ? 16 : 0;
    asm volatile("cp.async.cg.shared.global [%0], [%1], 16, %2;\n"
                 :: "r"(dst), "l"(src), "r"(sz));
}

__global__ __launch_bounds__(128, 3)
void bf16_gemm(const __nv_bfloat16* __restrict__ Ah, const __nv_bfloat16* __restrict__ Al,
               const __nv_bfloat16* __restrict__ Bh, const __nv_bfloat16* __restrict__ Bl,
               const float* __restrict__ bias, void* __restrict__ Cv,
               int M, int N, int K, int halfOut)
{
    extern __shared__ uint8_t sm8[];
    uint32_t smb;
    asm("{ .reg .u64 t; cvta.to.shared.u64 t, %1; cvt.u32.u64 %0, t; }" : "=r"(smb) : "l"(sm8));

    const int m0 = blockIdx.y * BM;
    const int n0 = blockIdx.x * BN;
    const int tid = threadIdx.x;
    const int lane = tid & 31, wm = tid >> 5;   // 4 warps, warp = m-slice
    const int r = lane >> 2, cc = lane & 3;

    float acc[2][8][4];
    #pragma unroll
    for (int i = 0; i < 2; i++)
        #pragma unroll
        for (int j = 0; j < 8; j++)
            #pragma unroll
            for (int t = 0; t < 4; t++) acc[i][j][t] = 0.f;

    const int nst = K / BK;

    auto LOAD = [&](int s, int buf) {
        uint32_t base = smb + buf * STAGE_B;
        const int k0 = s * BK;
        #pragma unroll
        for (int i = 0; i < 4; i++) {
            int c = tid + i * 128;
            int row = c >> 2, col = c & 3;
            bool p = (m0 + row) < M;
            long g = (long)(p ? (m0 + row) : 0) * K + k0 + col * 8;
            uint32_t so = swz((uint32_t)(row * 64 + col * 16));
            cp16(base + so, Ah + g, p);
            cp16(base + A_TILE_B + so, Al + g, p);
        }
        #pragma unroll
        for (int i = 0; i < 2; i++) {
            int c = tid + i * 128;
            int row = c >> 2, col = c & 3;
            bool p = (n0 + row) < N;
            long g = (long)(p ? (n0 + row) : 0) * K + k0 + col * 8;
            uint32_t so = swz((uint32_t)(row * 64 + col * 16));
            cp16(base + 2 * A_TILE_B + so, Bh + g, p);
            cp16(base + 2 * A_TILE_B + B_TILE_B + so, Bl + g, p);
        }
        asm volatile("cp.async.commit_group;\n" ::: "memory");
    };

    auto COMPUTE = [&](int buf) {
        uint32_t base = smb + buf * STAGE_B;
        #pragma unroll
        for (int kk = 0; kk < 2; kk++) {
            uint32_t ah[2][4], al[2][4];
            #pragma unroll
            for (int mt = 0; mt < 2; mt++) {
                int row = wm * 32 + mt * 16 + (lane & 15);
                uint32_t off = swz((uint32_t)(row * 64 + (kk * 2 + (lane >> 4)) * 16));
                ldsm4(ah[mt], base + off);
                ldsm4(al[mt], base + A_TILE_B + off);
            }
            #pragma unroll
            for (int nt2 = 0; nt2 < 4; nt2++) {
                int row = nt2 * 16 + (lane & 15);
                uint32_t off = swz((uint32_t)(row * 64 + (kk * 2 + (lane >> 4)) * 16));
                uint32_t bh[4], bl[4];
                ldsm4(bh, base + 2 * A_TILE_B + off);
                ldsm4(bl, base + 2 * A_TILE_B + B_TILE_B + off);
                #pragma unroll
                for (int mt = 0; mt < 2; mt++)
                    #pragma unroll
                    for (int hv = 0; hv < 2; hv++) {
                        int nt = nt2 * 2 + hv;
                        MMA16816(acc[mt][nt], ah[mt], bh[hv], bh[hv + 2]);
                        MMA16816(acc[mt][nt], al[mt], bh[hv], bh[hv + 2]);
                        MMA16816(acc[mt][nt], ah[mt], bl[hv], bl[hv + 2]);
                    }
            }
        }
    };

    LOAD(0, 0);
    if (nst > 1) LOAD(1, 1);
    for (int s = 0; s < nst; s++) {
        if (s + 1 < nst) { asm volatile("cp.async.wait_group 1;\n" ::: "memory"); }
        else             { asm volatile("cp.async.wait_group 0;\n" ::: "memory"); }
        __syncthreads();
        if (s + 2 < nst) LOAD(s + 2, (s + 2) % NSTAGE);
        COMPUTE(s % NSTAGE);
    }

    if (halfOut) {
        __half* C = (__half*)Cv;
        #pragma unroll
        for (int mt = 0; mt < 2; mt++) {
            int m = m0 + wm * 32 + mt * 16 + r;
            #pragma unroll
            for (int nt = 0; nt < 8; nt++) {
                int n = n0 + nt * 8 + cc * 2;
                const float* d = acc[mt][nt];
                if (n + 1 < N) {
                    float b0 = bias[n], b1 = bias[n + 1];
                    if (m < M)
                        *(__half2*)&C[(long)m * N + n] = __floats2half2_rn(d[0] + b0, d[1] + b1);
                    if (m + 8 < M)
                        *(__half2*)&C[(long)(m + 8) * N + n] = __floats2half2_rn(d[2] + b0, d[3] + b1);
                } else if (n < N) {
                    float b0 = bias[n];
                    if (m < M)     C[(long)m * N + n]       = __float2half_rn(d[0] + b0);
                    if (m + 8 < M) C[(long)(m + 8) * N + n] = __float2half_rn(d[2] + b0);
                }
            }
        }
    } else {
        float* C = (float*)Cv;
        #pragma unroll
        for (int mt = 0; mt < 2; mt++) {
            int m = m0 + wm * 32 + mt * 16 + r;
            #pragma unroll
            for (int nt = 0; nt < 8; nt++) {
                int n = n0 + nt * 8 + cc * 2;
                const float* d = acc[mt][nt];
                if (m < M) {
                    if (n < N)     C[(long)m * N + n]     = d[0] + bias[n];
                    if (n + 1 < N) C[(long)m * N + n + 1] = d[1] + bias[n + 1];
                }
                if (m + 8 < M) {
                    if (n < N)     C[(long)(m + 8) * N + n]     = d[2] + bias[n];
                    if (n + 1 < N) C[(long)(m + 8) * N + n + 1] = d[3] + bias[n + 1];
                }
            }
        }
    }
}

// ---------------- sampler v4: 4 samples per warp iteration, uint4 gathers ----------------
// 192 threads: warp = head. lane = g*8 + l8: subgroup g (0..3) owns sample j = jp*4+g,
// lane loads 8 fp16 channels (uint4, 16B; 8 lanes -> 128B aligned wavefront).
// Cross-subgroup combine via shfl_xor 8, 16.
__global__ __launch_bounds__(192)
void sample_kernel(const float* __restrict__ coor,
                   const float* __restrict__ cam2img,
                   const float* __restrict__ lidar2cam)
{
    const int q = blockIdx.x;
    const int b = blockIdx.y;
    const int tid = threadIdx.x;
    const int h    = tid >> 5;
    const int lane = tid & 31;
    const int g    = lane >> 3;
    const int l8   = lane & 7;

    __shared__ float  s_uv[2];
    __shared__ float  s_logit[NH_][NL_*NP_];
    __shared__ float  s_w[NH_][28];
    __shared__ int4   s_idx[NH_][28];
    __shared__ float4 s_bw[NH_][28];

    if (tid == 0) {
        const float* L  = lidar2cam + b * 16;
        const float* Kc = cam2img + b * 16;
        float p0 = coor[((long)b * NQ_ + q) * 3 + 0];
        float p1 = coor[((long)b * NQ_ + q) * 3 + 1];
        float p2 = coor[((long)b * NQ_ + q) * 3 + 2];
        float pc[3], pr[3];
        #pragma unroll
        for (int i = 0; i < 3; i++)
            pc[i] = L[i*4+0]*p0 + L[i*4+1]*p1 + L[i*4+2]*p2 + L[i*4+3];
        #pragma unroll
        for (int i = 0; i < 3; i++)
            pr[i] = Kc[i*4+0]*pc[0] + Kc[i*4+1]*pc[1] + Kc[i*4+2]*pc[2] + Kc[i*4+3];
        s_uv[0] = pr[0] / pr[2];
        s_uv[1] = pr[1] / pr[2];
    }
    __syncthreads();

    const long bq = (long)b * NQ_ + q;
    const float* oa = g_oa + bq * NOA_;

    if (tid < NATT_) {
        const int hh = tid / (NL_*NP_);
        const int j  = tid - hh * (NL_*NP_);
        const int l = j / NP_;
        const int p = j - l * NP_;

        s_logit[hh][j] = oa[NOFF_ + hh * (NL_*NP_) + j];

        const float* offp = &oa[hh * (NL_*NP_*2) + l * (NP_*2) + p * 2];
        float px = s_uv[0] * c_SX[l] + offp[0] - 0.5f;
        float py = s_uv[1] * c_SY[l] + offp[1] - 0.5f;
        float x0 = floorf(px), y0 = floorf(py);
        float fx = px - x0, fy = py - y0;
        const int wl = c_W[l], hl = c_H[l];
        const int base_l = b * TOTHW_ + c_OFF[l];

        int   idv[4];
        float bwv[4];
        #pragma unroll
        for (int c = 0; c < 4; c++) {
            int dx = c & 1, dy = c >> 1;
            float xi = x0 + dx, yi = y0 + dy;
            bool valid = (xi >= 0.f) && (xi < (float)wl) && (yi >= 0.f) && (yi < (float)hl);
            float wgt = (dx ? fx : 1.f - fx) * (dy ? fy : 1.f - fy);
            float xc = fminf(fmaxf(xi, 0.f), (float)(wl - 1));
            float yc = fminf(fmaxf(yi, 0.f), (float)(hl - 1));
            int pix = (int)yc * wl + (int)xc;
            idv[c] = (base_l + pix) * NHD_ + hh * DH_;
            bwv[c] = valid ? wgt : 0.f;
        }
        s_idx[hh][j] = make_int4(idv[0], idv[1], idv[2], idv[3]);
        s_bw[hh][j]  = make_float4(bwv[0], bwv[1], bwv[2], bwv[3]);
    }
    __syncthreads();

    if (tid < NATT_) {
        const int hh = tid / (NL_*NP_);
        const int j  = tid - hh * (NL_*NP_);
        float mx = -1e30f;
        #pragma unroll
        for (int jj = 0; jj < NL_*NP_; jj++) mx = fmaxf(mx, s_logit[hh][jj]);
        s_w[hh][j] = expf(s_logit[hh][j] - mx);
    }
    if (tid < NH_) {
        s_w[tid][27]   = 0.f;
        s_idx[tid][27] = s_idx[tid][26];
        s_bw[tid][27]  = make_float4(0.f, 0.f, 0.f, 0.f);
    }
    __syncthreads();

    float sum = 0.f;
    #pragma unroll
    for (int jj = 0; jj < NL_*NP_; jj++) sum += s_w[h][jj];
    const float rsum = 1.f / sum;

    float a[8];
    #pragma unroll
    for (int k = 0; k < 8; k++) a[k] = 0.f;

    #pragma unroll
    for (int jp = 0; jp < 7; jp++) {
        const int j = jp * 4 + g;
        const float aw = s_w[h][j] * rsum;
        const int4   id = s_idx[h][j];
        const float4 bw = s_bw[h][j];
        const int ids[4] = {id.x, id.y, id.z, id.w};
        const float bws[4] = {bw.x, bw.y, bw.z, bw.w};
        float t[8];
        #pragma unroll
        for (int k = 0; k < 8; k++) t[k] = 0.f;
        #pragma unroll
        for (int c = 0; c < 4; c++) {
            uint4 u = *reinterpret_cast<const uint4*>(g_vh16 + ids[c] + l8 * 8);
            float w = bws[c];
            float2 f0 = __half22float2(*reinterpret_cast<__half2*>(&u.x));
            float2 f1 = __half22float2(*reinterpret_cast<__half2*>(&u.y));
            float2 f2 = __half22float2(*reinterpret_cast<__half2*>(&u.z));
            float2 f3 = __half22float2(*reinterpret_cast<__half2*>(&u.w));
            t[0] += w * f0.x; t[1] += w * f0.y;
            t[2] += w * f1.x; t[3] += w * f1.y;
            t[4] += w * f2.x; t[5] += w * f2.y;
            t[6] += w * f3.x; t[7] += w * f3.y;
        }
        #pragma unroll
        for (int k = 0; k < 8; k++) a[k] += aw * t[k];
    }

    // reduce over the 4 subgroups
    #pragma unroll
    for (int k = 0; k < 8; k++) {
        a[k] += __shfl_xor_sync(0xffffffffu, a[k], 8);
        a[k] += __shfl_xor_sync(0xffffffffu, a[k], 16);
    }

    if (g == 0) {
        long oidx = bq * NHD_ + h * DH_ + l8 * 8;
        __nv_bfloat16 hi[8], lo[8];
        #pragma unroll
        for (int k = 0; k < 8; k++) {
            hi[k] = __float2bfloat16_rn(a[k]);
            lo[k] = __float2bfloat16_rn(a[k] - __bfloat162float(hi[k]));
        }
        *reinterpret_cast<uint4*>(&g_midh[oidx]) = *reinterpret_cast<uint4*>(hi);
        *reinterpret_cast<uint4*>(&g_midl[oidx]) = *reinterpret_cast<uint4*>(lo);
    }
}

// ---------------- host launcher ----------------
extern "C" void kernel_launch(void* const* d_in, const int* in_sizes, int n_in,
                              void* d_out, int out_size)
{
    const float* x         = (const float*)d_in[0];
    const float* pe        = (const float*)d_in[1];
    const float* coor      = (const float*)d_in[2];
    const float* cam2img   = (const float*)d_in[3];
    const float* lidar2cam = (const float*)d_in[4];
    const float* feat0     = (const float*)d_in[5];
    const float* feat1     = (const float*)d_in[6];
    const float* feat2     = (const float*)d_in[7];
    const float* W_value   = (const float*)d_in[8];
    const float* b_value   = (const float*)d_in[9];
    const float* W_off     = (const float*)d_in[10];
    const float* b_off     = (const float*)d_in[11];
    const float* W_attn    = (const float*)d_in[12];
    const float* b_attn    = (const float*)d_in[13];
    const float* W_out     = (const float*)d_in[14];
    const float* b_out     = (const float*)d_in[15];
    float* out = (float*)d_out;

    float *poa, *pboa;
    __half* pv16;
    __nv_bfloat16 *pqh, *pql, *pfh, *pfl, *pmidh, *pmidl, *pwh, *pwl;
    cudaGetSymbolAddress((void**)&pv16, g_vh16);
    cudaGetSymbolAddress((void**)&poa, g_oa);
    cudaGetSymbolAddress((void**)&pboa, g_boa);
    cudaGetSymbolAddress((void**)&pqh, g_qh);
    cudaGetSymbolAddress((void**)&pql, g_ql);
    cudaGetSymbolAddress((void**)&pfh, g_fh);
    cudaGetSymbolAddress((void**)&pfl, g_fl);
    cudaGetSymbolAddress((void**)&pmidh, g_midh);
    cudaGetSymbolAddress((void**)&pmidl, g_midl);
    cudaGetSymbolAddress((void**)&pwh, g_wh);
    cudaGetSymbolAddress((void**)&pwl, g_wl);

    static bool attrSet = false;
    if (!attrSet) {
        cudaFuncSetAttribute(bf16_gemm, cudaFuncAttributeMaxDynamicSharedMemorySize, GEMM_SMEM);
        attrSet = true;
    }

    // 1: weight transposes + bias concat
    {
        dim3 grid(12, 12, 5);
        prep_weights_kernel<<<grid, 256>>>(W_value, W_off, W_attn, W_out, b_off, b_attn);
    }
    // 2: q = x + pe, split
    {
        int n4 = B_ * NQ_ * DM_ / 4;
        add_split_kernel<<<(n4 + 255) / 256, 256>>>(x, pe, pqh, pql, n4);
    }
    // 3: fused feature transpose+split
    {
        dim3 grid(315, 8, B_);
        feat_transpose_kernel<<<grid, 256>>>(feat0, feat1, feat2);
    }
    // 4: value projection GEMM (fp16 out)
    {
        dim3 grid(NHD_ / BN, (B_ * TOTHW_ + BM - 1) / BM);
        bf16_gemm<<<grid, 128, GEMM_SMEM>>>(pfh, pfl, pwh + WV_OFF, pwl + WV_OFF,
                                            b_value, pv16, B_ * TOTHW_, NHD_, DM_, 1);
    }
    // 5: combined offsets+attn GEMM
    {
        dim3 grid((NOA_ + BN - 1) / BN, (B_ * NQ_) / BM);
        bf16_gemm<<<grid, 128, GEMM_SMEM>>>(pqh, pql, pwh + WOA_OFF, pwl + WOA_OFF,
                                            pboa, poa, B_ * NQ_, NOA_, DM_, 0);
    }
    // 6: sampler
    {
        dim3 grid(NQ_, B_);
        sample_kernel<<<grid, 192>>>(coor, cam2img, lidar2cam);
    }
    // 7: output GEMM
    {
        dim3 grid(DM_ / BN, (B_ * NQ_) / BM);
        bf16_gemm<<<grid, 128, GEMM_SMEM>>>(pmidh, pmidl, pwh + WOUT_OFF, pwl + WOUT_OFF,
                                            b_out, out, B_ * NQ_, DM_, NHD_, 0);
    }
}

// round 11
// speedup vs baseline: 1.8237x; 1.1725x over previous
#include <cuda_runtime.h>
#include <cuda_bf16.h>
#include <cuda_fp16.h>
#include <math.h>
#include <stdint.h>

// ---------------- problem constants ----------------
#define B_   2
#define NQ_  8192
#define DM_  256
#define NH_  6
#define DH_  64
#define NL_  3
#define NP_  9
#define NHD_ (NH_*DH_)            // 384
#define NOFF_ (NH_*NL_*NP_*2)     // 324
#define NATT_ (NH_*NL_*NP_)       // 162
#define NOA_  (NOFF_ + NATT_)     // 486
#define TOTHW_ 10080              // 7680+1920+480

// level tables
__device__ __constant__ int   c_W[3]   = {160, 80, 40};
__device__ __constant__ int   c_H[3]   = {48, 24, 12};
__device__ __constant__ int   c_OFF[3] = {0, 7680, 9600};
__device__ __constant__ float c_SX[3]  = {160.f/1280.f, 80.f/1280.f, 40.f/1280.f};
__device__ __constant__ float c_SY[3]  = {48.f/384.f, 24.f/384.f, 12.f/384.f};

// ---------------- scratch (no allocs allowed) ----------------
__device__ __half g_vh16[(size_t)B_ * TOTHW_ * NHD_];   // value projection (fp16)
__device__ float g_oa  [(size_t)B_ * NQ_ * NOA_];       // offsets(324) | attn(162)
__device__ float g_boa [NOA_];

// single fp16 A-planes
__device__ __half g_q16 [(size_t)B_ * NQ_ * DM_];
__device__ __half g_f16 [(size_t)B_ * TOTHW_ * DM_];
__device__ __half g_mid16[(size_t)B_ * NQ_ * NHD_];

// weights transposed [N][K], fp16 hi/lo split: Wv(384x256) | Woa(486x256) | Wout(256x384)
#define WV_OFF   0
#define WOA_OFF  (384*256)
#define WOUT_OFF (WOA_OFF + NOA_*256)
#define WTOT_    (WOUT_OFF + 256*384)
__device__ __half g_wh[WTOT_];
__device__ __half g_wl[WTOT_];

// ================= prep kernels =================
__global__ __launch_bounds__(256)
void add_half_kernel(const float* __restrict__ x, const float* __restrict__ pe,
                     __half* __restrict__ o, int n4)
{
    int i = blockIdx.x * blockDim.x + threadIdx.x;
    if (i >= n4) return;
    float4 a = reinterpret_cast<const float4*>(x)[i];
    float4 b = reinterpret_cast<const float4*>(pe)[i];
    __half h[4];
    h[0] = __float2half_rn(a.x + b.x);
    h[1] = __float2half_rn(a.y + b.y);
    h[2] = __float2half_rn(a.z + b.z);
    h[3] = __float2half_rn(a.w + b.w);
    *reinterpret_cast<uint2*>(o + (size_t)i*4) = *reinterpret_cast<uint2*>(h);
}

// fused feature transpose: all 3 levels, both batches -> fp16 [b][pix][256]
__global__ __launch_bounds__(256)
void feat_transpose_kernel(const float* __restrict__ f0, const float* __restrict__ f1,
                           const float* __restrict__ f2)
{
    __shared__ float t[32][33];
    const int b = blockIdx.z;
    int xt = blockIdx.x;
    int l, c0;
    const float* in;
    int hwl;
    if (xt < 240)      { l = 0; c0 = xt * 32;         in = f0; hwl = 7680; }
    else if (xt < 300) { l = 1; c0 = (xt - 240) * 32; in = f1; hwl = 1920; }
    else               { l = 2; c0 = (xt - 300) * 32; in = f2; hwl = 480;  }
    in += (long)b * DM_ * hwl;
    const int r0 = blockIdx.y * 32;
    const int tx = threadIdx.x & 31, ty = threadIdx.x >> 5;

    #pragma unroll
    for (int i = 0; i < 32; i += 8)
        t[ty + i][tx] = in[(long)(r0 + ty + i) * hwl + c0 + tx];
    __syncthreads();
    const long outBase = ((long)b * TOTHW_ + c_OFF[l] + c0) * DM_ + r0;
    #pragma unroll
    for (int i = 0; i < 32; i += 8) {
        long o = outBase + (long)(ty + i) * DM_ + tx;
        g_f16[o] = __float2half_rn(t[tx][ty + i]);
    }
}

// weight transposes + fp16 hi/lo split + bias concat
__global__ __launch_bounds__(256)
void prep_weights_kernel(const float* __restrict__ Wv, const float* __restrict__ Woff,
                         const float* __restrict__ Wattn, const float* __restrict__ Wout,
                         const float* __restrict__ boff, const float* __restrict__ battn)
{
    const int z = blockIdx.z;
    if (z == 4) {
        if (blockIdx.y != 0 || blockIdx.x > 1) return;
        int i = blockIdx.x * 256 + threadIdx.x;
        if (i < NOFF_) g_boa[i] = boff[i];
        else if (i < NOA_) g_boa[i] = battn[i - NOFF_];
        return;
    }
    int R, C; const float* in; long base; int rowOff = 0;
    if (z == 0)      { in = Wv;    R = 256; C = 384; base = WV_OFF; }
    else if (z == 1) { in = Woff;  R = 256; C = 324; base = WOA_OFF; }
    else if (z == 2) { in = Wattn; R = 256; C = 162; base = WOA_OFF; rowOff = 324; }
    else             { in = Wout;  R = 384; C = 256; base = WOUT_OFF; }

    const int c0 = blockIdx.x * 32, r0 = blockIdx.y * 32;
    if (c0 >= C || r0 >= R) return;

    __shared__ float t[32][33];
    const int tx = threadIdx.x & 31, ty = threadIdx.x >> 5;
    #pragma unroll
    for (int i = 0; i < 32; i += 8) {
        int r = r0 + ty + i, c = c0 + tx;
        t[ty + i][tx] = (r < R && c < C) ? in[(long)r * C + c] : 0.f;
    }
    __syncthreads();
    #pragma unroll
    for (int i = 0; i < 32; i += 8) {
        int c = c0 + ty + i, r = r0 + tx;
        if (c < C && r < R) {
            float v = t[tx][ty + i];
            __half h = __float2half_rn(v);
            long o = base + (long)(rowOff + c) * R + r;
            g_wh[o] = h;
            g_wl[o] = __float2half_rn(v - __half2float(h));
        }
    }
}

// ================= fp16 tensor-core GEMM =================
// C[M,N] = A16[M,K] @ (Bh+Bl)[N,K]^T + bias   (A single fp16, B 2-term split)
// 128 threads, 4 warps, warp tile 32x64, BM=128 BN=64 BK=32, 3-stage cp.async
#define BM 128
#define BN 64
#define BK 32
#define A_TILE_B (BM*BK*2)                 // 8192
#define B_TILE_B (BN*BK*2)                 // 4096
#define STAGE_B  (A_TILE_B + 2*B_TILE_B)   // 16384
#define NSTAGE 3
#define GEMM_SMEM (NSTAGE*STAGE_B)         // 49152

#define MMAF16(d, a, b0v, b1v) \
  asm volatile("mma.sync.aligned.m16n8k16.row.col.f32.f16.f16.f32 " \
    "{%0,%1,%2,%3},{%4,%5,%6,%7},{%8,%9},{%0,%1,%2,%3};" \
    : "+f"((d)[0]), "+f"((d)[1]), "+f"((d)[2]), "+f"((d)[3]) \
    : "r"((a)[0]), "r"((a)[1]), "r"((a)[2]), "r"((a)[3]), "r"(b0v), "r"(b1v))

__device__ __forceinline__ uint32_t swz(uint32_t off) {
    return off ^ ((off >> 3) & 0x30);
}
__device__ __forceinline__ void ldsm4(uint32_t (&r)[4], uint32_t addr) {
    asm volatile("ldmatrix.sync.aligned.m8n8.x4.shared.b16 {%0,%1,%2,%3}, [%4];"
        : "=r"(r[0]), "=r"(r[1]), "=r"(r[2]), "=r"(r[3]) : "r"(addr));
}
__device__ __forceinline__ void cp16(uint32_t dst, const void* src, bool pred) {
    int sz = pred ? 16 : 0;
    asm volatile("cp.async.cg.shared.global [%0], [%1], 16, %2;\n"
                 :: "r"(dst), "l"(src), "r"(sz));
}

__global__ __launch_bounds__(128, 4)
void f16_gemm(const __half* __restrict__ A,
              const __half* __restrict__ Bh, const __half* __restrict__ Bl,
              const float* __restrict__ bias, void* __restrict__ Cv,
              int M, int N, int K, int halfOut)
{
    extern __shared__ uint8_t sm8[];
    uint32_t smb;
    asm("{ .reg .u64 t; cvta.to.shared.u64 t, %1; cvt.u32.u64 %0, t; }" : "=r"(smb) : "l"(sm8));

    const int m0 = blockIdx.y * BM;
    const int n0 = blockIdx.x * BN;
    const int tid = threadIdx.x;
    const int lane = tid & 31, wm = tid >> 5;
    const int r = lane >> 2, cc = lane & 3;

    float acc[2][8][4];
    #pragma unroll
    for (int i = 0; i < 2; i++)
        #pragma unroll
        for (int j = 0; j < 8; j++)
            #pragma unroll
            for (int t = 0; t < 4; t++) acc[i][j][t] = 0.f;

    const int nst = K / BK;

    auto LOAD = [&](int s, int buf) {
        uint32_t base = smb + buf * STAGE_B;
        const int k0 = s * BK;
        #pragma unroll
        for (int i = 0; i < 4; i++) {
            int c = tid + i * 128;
            int row = c >> 2, col = c & 3;
            bool p = (m0 + row) < M;
            long g = (long)(p ? (m0 + row) : 0) * K + k0 + col * 8;
            uint32_t so = swz((uint32_t)(row * 64 + col * 16));
            cp16(base + so, A + g, p);
        }
        #pragma unroll
        for (int i = 0; i < 2; i++) {
            int c = tid + i * 128;
            int row = c >> 2, col = c & 3;
            bool p = (n0 + row) < N;
            long g = (long)(p ? (n0 + row) : 0) * K + k0 + col * 8;
            uint32_t so = swz((uint32_t)(row * 64 + col * 16));
            cp16(base + A_TILE_B + so, Bh + g, p);
            cp16(base + A_TILE_B + B_TILE_B + so, Bl + g, p);
        }
        asm volatile("cp.async.commit_group;\n" ::: "memory");
    };

    auto COMPUTE = [&](int buf) {
        uint32_t base = smb + buf * STAGE_B;
        #pragma unroll
        for (int kk = 0; kk < 2; kk++) {
            uint32_t a[2][4];
            #pragma unroll
            for (int mt = 0; mt < 2; mt++) {
                int row = wm * 32 + mt * 16 + (lane & 15);
                uint32_t off = swz((uint32_t)(row * 64 + (kk * 2 + (lane >> 4)) * 16));
                ldsm4(a[mt], base + off);
            }
            #pragma unroll
            for (int nt2 = 0; nt2 < 4; nt2++) {
                int row = nt2 * 16 + (lane & 15);
                uint32_t off = swz((uint32_t)(row * 64 + (kk * 2 + (lane >> 4)) * 16));
                uint32_t bh[4], bl[4];
                ldsm4(bh, base + A_TILE_B + off);
                ldsm4(bl, base + A_TILE_B + B_TILE_B + off);
                #pragma unroll
                for (int mt = 0; mt < 2; mt++)
                    #pragma unroll
                    for (int hv = 0; hv < 2; hv++) {
                        int nt = nt2 * 2 + hv;
                        MMAF16(acc[mt][nt], a[mt], bh[hv], bh[hv + 2]);
                        MMAF16(acc[mt][nt], a[mt], bl[hv], bl[hv + 2]);
                    }
            }
        }
    };

    LOAD(0, 0);
    if (nst > 1) LOAD(1, 1);
    for (int s = 0; s < nst; s++) {
        if (s + 1 < nst) { asm volatile("cp.async.wait_group 1;\n" ::: "memory"); }
        else             { asm volatile("cp.async.wait_group 0;\n" ::: "memory"); }
        __syncthreads();
        if (s + 2 < nst) LOAD(s + 2, (s + 2) % NSTAGE);
        COMPUTE(s % NSTAGE);
    }

    if (halfOut) {
        __half* C = (__half*)Cv;
        #pragma unroll
        for (int mt = 0; mt < 2; mt++) {
            int m = m0 + wm * 32 + mt * 16 + r;
            #pragma unroll
            for (int nt = 0; nt < 8; nt++) {
                int n = n0 + nt * 8 + cc * 2;
                const float* d = acc[mt][nt];
                if (n + 1 < N) {
                    float b0 = bias[n], b1 = bias[n + 1];
                    if (m < M)
                        *(__half2*)&C[(long)m * N + n] = __floats2half2_rn(d[0] + b0, d[1] + b1);
                    if (m + 8 < M)
                        *(__half2*)&C[(long)(m + 8) * N + n] = __floats2half2_rn(d[2] + b0, d[3] + b1);
                } else if (n < N) {
                    float b0 = bias[n];
                    if (m < M)     C[(long)m * N + n]       = __float2half_rn(d[0] + b0);
                    if (m + 8 < M) C[(long)(m + 8) * N + n] = __float2half_rn(d[2] + b0);
                }
            }
        }
    } else {
        float* C = (float*)Cv;
        #pragma unroll
        for (int mt = 0; mt < 2; mt++) {
            int m = m0 + wm * 32 + mt * 16 + r;
            #pragma unroll
            for (int nt = 0; nt < 8; nt++) {
                int n = n0 + nt * 8 + cc * 2;
                const float* d = acc[mt][nt];
                if (m < M) {
                    if (n < N)     C[(long)m * N + n]     = d[0] + bias[n];
                    if (n + 1 < N) C[(long)m * N + n + 1] = d[1] + bias[n + 1];
                }
                if (m + 8 < M) {
                    if (n < N)     C[(long)(m + 8) * N + n]     = d[2] + bias[n];
                    if (n + 1 < N) C[(long)(m + 8) * N + n + 1] = d[3] + bias[n + 1];
                }
            }
        }
    }
}

// ---------------- sampler: 4 samples per warp iteration, uint4 gathers ----------------
__global__ __launch_bounds__(192)
void sample_kernel(const float* __restrict__ coor,
                   const float* __restrict__ cam2img,
                   const float* __restrict__ lidar2cam)
{
    const int q = blockIdx.x;
    const int b = blockIdx.y;
    const int tid = threadIdx.x;
    const int h    = tid >> 5;
    const int lane = tid & 31;
    const int g    = lane >> 3;
    const int l8   = lane & 7;

    __shared__ float  s_uv[2];
    __shared__ float  s_logit[NH_][NL_*NP_];
    __shared__ float  s_w[NH_][28];
    __shared__ int4   s_idx[NH_][28];
    __shared__ float4 s_bw[NH_][28];

    if (tid == 0) {
        const float* L  = lidar2cam + b * 16;
        const float* Kc = cam2img + b * 16;
        float p0 = coor[((long)b * NQ_ + q) * 3 + 0];
        float p1 = coor[((long)b * NQ_ + q) * 3 + 1];
        float p2 = coor[((long)b * NQ_ + q) * 3 + 2];
        float pc[3], pr[3];
        #pragma unroll
        for (int i = 0; i < 3; i++)
            pc[i] = L[i*4+0]*p0 + L[i*4+1]*p1 + L[i*4+2]*p2 + L[i*4+3];
        #pragma unroll
        for (int i = 0; i < 3; i++)
            pr[i] = Kc[i*4+0]*pc[0] + Kc[i*4+1]*pc[1] + Kc[i*4+2]*pc[2] + Kc[i*4+3];
        s_uv[0] = pr[0] / pr[2];
        s_uv[1] = pr[1] / pr[2];
    }
    __syncthreads();

    const long bq = (long)b * NQ_ + q;
    const float* oa = g_oa + bq * NOA_;

    if (tid < NATT_) {
        const int hh = tid / (NL_*NP_);
        const int j  = tid - hh * (NL_*NP_);
        const int l = j / NP_;
        const int p = j - l * NP_;

        s_logit[hh][j] = oa[NOFF_ + hh * (NL_*NP_) + j];

        const float* offp = &oa[hh * (NL_*NP_*2) + l * (NP_*2) + p * 2];
        float px = s_uv[0] * c_SX[l] + offp[0] - 0.5f;
        float py = s_uv[1] * c_SY[l] + offp[1] - 0.5f;
        float x0 = floorf(px), y0 = floorf(py);
        float fx = px - x0, fy = py - y0;
        const int wl = c_W[l], hl = c_H[l];
        const int base_l = b * TOTHW_ + c_OFF[l];

        int   idv[4];
        float bwv[4];
        #pragma unroll
        for (int c = 0; c < 4; c++) {
            int dx = c & 1, dy = c >> 1;
            float xi = x0 + dx, yi = y0 + dy;
            bool valid = (xi >= 0.f) && (xi < (float)wl) && (yi >= 0.f) && (yi < (float)hl);
            float wgt = (dx ? fx : 1.f - fx) * (dy ? fy : 1.f - fy);
            float xc = fminf(fmaxf(xi, 0.f), (float)(wl - 1));
            float yc = fminf(fmaxf(yi, 0.f), (float)(hl - 1));
            int pix = (int)yc * wl + (int)xc;
            idv[c] = (base_l + pix) * NHD_ + hh * DH_;
            bwv[c] = valid ? wgt : 0.f;
        }
        s_idx[hh][j] = make_int4(idv[0], idv[1], idv[2], idv[3]);
        s_bw[hh][j]  = make_float4(bwv[0], bwv[1], bwv[2], bwv[3]);
    }
    __syncthreads();

    if (tid < NATT_) {
        const int hh = tid / (NL_*NP_);
        const int j  = tid - hh * (NL_*NP_);
        float mx = -1e30f;
        #pragma unroll
        for (int jj = 0; jj < NL_*NP_; jj++) mx = fmaxf(mx, s_logit[hh][jj]);
        s_w[hh][j] = expf(s_logit[hh][j] - mx);
    }
    if (tid < NH_) {
        s_w[tid][27]   = 0.f;
        s_idx[tid][27] = s_idx[tid][26];
        s_bw[tid][27]  = make_float4(0.f, 0.f, 0.f, 0.f);
    }
    __syncthreads();

    float sum = 0.f;
    #pragma unroll
    for (int jj = 0; jj < NL_*NP_; jj++) sum += s_w[h][jj];
    const float rsum = 1.f / sum;

    float a[8];
    #pragma unroll
    for (int k = 0; k < 8; k++) a[k] = 0.f;

    #pragma unroll
    for (int jp = 0; jp < 7; jp++) {
        const int j = jp * 4 + g;
        const float aw = s_w[h][j] * rsum;
        const int4   id = s_idx[h][j];
        const float4 bw = s_bw[h][j];
        const int ids[4] = {id.x, id.y, id.z, id.w};
        const float bws[4] = {bw.x, bw.y, bw.z, bw.w};
        float t[8];
        #pragma unroll
        for (int k = 0; k < 8; k++) t[k] = 0.f;
        #pragma unroll
        for (int c = 0; c < 4; c++) {
            uint4 u = *reinterpret_cast<const uint4*>(g_vh16 + ids[c] + l8 * 8);
            float w = bws[c];
            float2 f0 = __half22float2(*reinterpret_cast<__half2*>(&u.x));
            float2 f1 = __half22float2(*reinterpret_cast<__half2*>(&u.y));
            float2 f2 = __half22float2(*reinterpret_cast<__half2*>(&u.z));
            float2 f3 = __half22float2(*reinterpret_cast<__half2*>(&u.w));
            t[0] += w * f0.x; t[1] += w * f0.y;
            t[2] += w * f1.x; t[3] += w * f1.y;
            t[4] += w * f2.x; t[5] += w * f2.y;
            t[6] += w * f3.x; t[7] += w * f3.y;
        }
        #pragma unroll
        for (int k = 0; k < 8; k++) a[k] += aw * t[k];
    }

    #pragma unroll
    for (int k = 0; k < 8; k++) {
        a[k] += __shfl_xor_sync(0xffffffffu, a[k], 8);
        a[k] += __shfl_xor_sync(0xffffffffu, a[k], 16);
    }

    if (g == 0) {
        long oidx = bq * NHD_ + h * DH_ + l8 * 8;
        __half hv[8];
        #pragma unroll
        for (int k = 0; k < 8; k++) hv[k] = __float2half_rn(a[k]);
        *reinterpret_cast<uint4*>(&g_mid16[oidx]) = *reinterpret_cast<uint4*>(hv);
    }
}

// ---------------- host launcher ----------------
extern "C" void kernel_launch(void* const* d_in, const int* in_sizes, int n_in,
                              void* d_out, int out_size)
{
    const float* x         = (const float*)d_in[0];
    const float* pe        = (const float*)d_in[1];
    const float* coor      = (const float*)d_in[2];
    const float* cam2img   = (const float*)d_in[3];
    const float* lidar2cam = (const float*)d_in[4];
    const float* feat0     = (const float*)d_in[5];
    const float* feat1     = (const float*)d_in[6];
    const float* feat2     = (const float*)d_in[7];
    const float* W_value   = (const float*)d_in[8];
    const float* b_value   = (const float*)d_in[9];
    const float* W_off     = (const float*)d_in[10];
    const float* b_off     = (const float*)d_in[11];
    const float* W_attn    = (const float*)d_in[12];
    const float* b_attn    = (const float*)d_in[13];
    const float* W_out     = (const float*)d_in[14];
    const float* b_out     = (const float*)d_in[15];
    float* out = (float*)d_out;

    float *poa, *pboa;
    __half *pv16, *pq16, *pf16, *pmid16, *pwh, *pwl;
    cudaGetSymbolAddress((void**)&pv16, g_vh16);
    cudaGetSymbolAddress((void**)&poa, g_oa);
    cudaGetSymbolAddress((void**)&pboa, g_boa);
    cudaGetSymbolAddress((void**)&pq16, g_q16);
    cudaGetSymbolAddress((void**)&pf16, g_f16);
    cudaGetSymbolAddress((void**)&pmid16, g_mid16);
    cudaGetSymbolAddress((void**)&pwh, g_wh);
    cudaGetSymbolAddress((void**)&pwl, g_wl);

    static bool attrSet = false;
    if (!attrSet) {
        cudaFuncSetAttribute(f16_gemm, cudaFuncAttributeMaxDynamicSharedMemorySize, GEMM_SMEM);
        attrSet = true;
    }

    // 1: weight transposes + bias concat
    {
        dim3 grid(12, 12, 5);
        prep_weights_kernel<<<grid, 256>>>(W_value, W_off, W_attn, W_out, b_off, b_attn);
    }
    // 2: q = x + pe (fp16)
    {
        int n4 = B_ * NQ_ * DM_ / 4;
        add_half_kernel<<<(n4 + 255) / 256, 256>>>(x, pe, pq16, n4);
    }
    // 3: fused feature transpose (fp16)
    {
        dim3 grid(315, 8, B_);
        feat_transpose_kernel<<<grid, 256>>>(feat0, feat1, feat2);
    }
    // 4: value projection GEMM (fp16 out)
    {
        dim3 grid(NHD_ / BN, (B_ * TOTHW_ + BM - 1) / BM);
        f16_gemm<<<grid, 128, GEMM_SMEM>>>(pf16, pwh + WV_OFF, pwl + WV_OFF,
                                           b_value, pv16, B_ * TOTHW_, NHD_, DM_, 1);
    }
    // 5: combined offsets+attn GEMM
    {
        dim3 grid((NOA_ + BN - 1) / BN, (B_ * NQ_) / BM);
        f16_gemm<<<grid, 128, GEMM_SMEM>>>(pq16, pwh + WOA_OFF, pwl + WOA_OFF,
                                           pboa, poa, B_ * NQ_, NOA_, DM_, 0);
    }
    // 6: sampler
    {
        dim3 grid(NQ_, B_);
        sample_kernel<<<grid, 192>>>(coor, cam2img, lidar2cam);
    }
    // 7: output GEMM
    {
        dim3 grid(DM_ / BN, (B_ * NQ_) / BM);
        f16_gemm<<<grid, 128, GEMM_SMEM>>>(pmid16, pwh + WOUT_OFF, pwl + WOUT_OFF,
                                           b_out, out, B_ * NQ_, DM_, NHD_, 0);
    }
}

// round 12
// speedup vs baseline: 1.8744x; 1.0278x over previous
#include <cuda_runtime.h>
#include <cuda_bf16.h>
#include <cuda_fp16.h>
#include <math.h>
#include <stdint.h>

// ---------------- problem constants ----------------
#define B_   2
#define NQ_  8192
#define DM_  256
#define NH_  6
#define DH_  64
#define NL_  3
#define NP_  9
#define NHD_ (NH_*DH_)            // 384
#define NOFF_ (NH_*NL_*NP_*2)     // 324
#define NATT_ (NH_*NL_*NP_)       // 162
#define NOA_  (NOFF_ + NATT_)     // 486
#define TOTHW_ 10080              // 7680+1920+480

// level tables
__device__ __constant__ int   c_W[3]   = {160, 80, 40};
__device__ __constant__ int   c_H[3]   = {48, 24, 12};
__device__ __constant__ int   c_OFF[3] = {0, 7680, 9600};
__device__ __constant__ float c_SX[3]  = {160.f/1280.f, 80.f/1280.f, 40.f/1280.f};
__device__ __constant__ float c_SY[3]  = {48.f/384.f, 24.f/384.f, 12.f/384.f};

// ---------------- scratch (no allocs allowed) ----------------
__device__ __half g_vh16[(size_t)B_ * TOTHW_ * NHD_];   // value projection (fp16)
__device__ float g_oa  [(size_t)B_ * NQ_ * NOA_];       // offsets(324) | attn(162)
__device__ float g_boa [NOA_];

// single fp16 A-planes
__device__ __half g_q16 [(size_t)B_ * NQ_ * DM_];
__device__ __half g_f16 [(size_t)B_ * TOTHW_ * DM_];
__device__ __half g_mid16[(size_t)B_ * NQ_ * NHD_];

// weights transposed [N][K], fp16 hi/lo split: Wv(384x256) | Woa(486x256) | Wout(256x384)
#define WV_OFF   0
#define WOA_OFF  (384*256)
#define WOUT_OFF (WOA_OFF + NOA_*256)
#define WTOT_    (WOUT_OFF + 256*384)
__device__ __half g_wh[WTOT_];
__device__ __half g_wl[WTOT_];

// ================= prep kernels =================
__global__ __launch_bounds__(256)
void add_half_kernel(const float* __restrict__ x, const float* __restrict__ pe,
                     __half* __restrict__ o, int n4)
{
    int i = blockIdx.x * blockDim.x + threadIdx.x;
    if (i >= n4) return;
    float4 a = reinterpret_cast<const float4*>(x)[i];
    float4 b = reinterpret_cast<const float4*>(pe)[i];
    __half h[4];
    h[0] = __float2half_rn(a.x + b.x);
    h[1] = __float2half_rn(a.y + b.y);
    h[2] = __float2half_rn(a.z + b.z);
    h[3] = __float2half_rn(a.w + b.w);
    *reinterpret_cast<uint2*>(o + (size_t)i*4) = *reinterpret_cast<uint2*>(h);
}

// fused feature transpose: all 3 levels, both batches -> fp16 [b][pix][256]
__global__ __launch_bounds__(256)
void feat_transpose_kernel(const float* __restrict__ f0, const float* __restrict__ f1,
                           const float* __restrict__ f2)
{
    __shared__ float t[32][33];
    const int b = blockIdx.z;
    int xt = blockIdx.x;
    int l, c0;
    const float* in;
    int hwl;
    if (xt < 240)      { l = 0; c0 = xt * 32;         in = f0; hwl = 7680; }
    else if (xt < 300) { l = 1; c0 = (xt - 240) * 32; in = f1; hwl = 1920; }
    else               { l = 2; c0 = (xt - 300) * 32; in = f2; hwl = 480;  }
    in += (long)b * DM_ * hwl;
    const int r0 = blockIdx.y * 32;
    const int tx = threadIdx.x & 31, ty = threadIdx.x >> 5;

    #pragma unroll
    for (int i = 0; i < 32; i += 8)
        t[ty + i][tx] = in[(long)(r0 + ty + i) * hwl + c0 + tx];
    __syncthreads();
    const long outBase = ((long)b * TOTHW_ + c_OFF[l] + c0) * DM_ + r0;
    #pragma unroll
    for (int i = 0; i < 32; i += 8) {
        long o = outBase + (long)(ty + i) * DM_ + tx;
        g_f16[o] = __float2half_rn(t[tx][ty + i]);
    }
}

// weight transposes + fp16 hi/lo split + bias concat
__global__ __launch_bounds__(256)
void prep_weights_kernel(const float* __restrict__ Wv, const float* __restrict__ Woff,
                         const float* __restrict__ Wattn, const float* __restrict__ Wout,
                         const float* __restrict__ boff, const float* __restrict__ battn)
{
    const int z = blockIdx.z;
    if (z == 4) {
        if (blockIdx.y != 0 || blockIdx.x > 1) return;
        int i = blockIdx.x * 256 + threadIdx.x;
        if (i < NOFF_) g_boa[i] = boff[i];
        else if (i < NOA_) g_boa[i] = battn[i - NOFF_];
        return;
    }
    int R, C; const float* in; long base; int rowOff = 0;
    if (z == 0)      { in = Wv;    R = 256; C = 384; base = WV_OFF; }
    else if (z == 1) { in = Woff;  R = 256; C = 324; base = WOA_OFF; }
    else if (z == 2) { in = Wattn; R = 256; C = 162; base = WOA_OFF; rowOff = 324; }
    else             { in = Wout;  R = 384; C = 256; base = WOUT_OFF; }

    const int c0 = blockIdx.x * 32, r0 = blockIdx.y * 32;
    if (c0 >= C || r0 >= R) return;

    __shared__ float t[32][33];
    const int tx = threadIdx.x & 31, ty = threadIdx.x >> 5;
    #pragma unroll
    for (int i = 0; i < 32; i += 8) {
        int r = r0 + ty + i, c = c0 + tx;
        t[ty + i][tx] = (r < R && c < C) ? in[(long)r * C + c] : 0.f;
    }
    __syncthreads();
    #pragma unroll
    for (int i = 0; i < 32; i += 8) {
        int c = c0 + ty + i, r = r0 + tx;
        if (c < C && r < R) {
            float v = t[tx][ty + i];
            __half h = __float2half_rn(v);
            long o = base + (long)(rowOff + c) * R + r;
            g_wh[o] = h;
            g_wl[o] = __float2half_rn(v - __half2float(h));
        }
    }
}

// ================= fp16 tensor-core GEMM (dual-descriptor, pipelined) =================
#define BM 128
#define BN 64
#define BK 32
#define A_TILE_B (BM*BK*2)                 // 8192
#define B_TILE_B (BN*BK*2)                 // 4096
#define STAGE_B  (A_TILE_B + 2*B_TILE_B)   // 16384
#define NSTAGE 3
#define GEMM_SMEM (NSTAGE*STAGE_B)         // 49152

struct GDesc {
    const __half* A;
    const __half* Bh;
    const __half* Bl;
    const float*  bias;
    void*         C;
    int M, N, K, halfOut, nbx;
};

#define MMAF16(d, a, b0v, b1v) \
  asm volatile("mma.sync.aligned.m16n8k16.row.col.f32.f16.f16.f32 " \
    "{%0,%1,%2,%3},{%4,%5,%6,%7},{%8,%9},{%0,%1,%2,%3};" \
    : "+f"((d)[0]), "+f"((d)[1]), "+f"((d)[2]), "+f"((d)[3]) \
    : "r"((a)[0]), "r"((a)[1]), "r"((a)[2]), "r"((a)[3]), "r"(b0v), "r"(b1v))

__device__ __forceinline__ uint32_t swz(uint32_t off) {
    return off ^ ((off >> 3) & 0x30);
}
__device__ __forceinline__ void ldsm4(uint32_t (&r)[4], uint32_t addr) {
    asm volatile("ldmatrix.sync.aligned.m8n8.x4.shared.b16 {%0,%1,%2,%3}, [%4];"
        : "=r"(r[0]), "=r"(r[1]), "=r"(r[2]), "=r"(r[3]) : "r"(addr));
}
__device__ __forceinline__ void cp16(uint32_t dst, const void* src, bool pred) {
    int sz = pred ? 16 : 0;
    asm volatile("cp.async.cg.shared.global [%0], [%1], 16, %2;\n"
                 :: "r"(dst), "l"(src), "r"(sz));
}

__global__ __launch_bounds__(128, 4)
void f16_gemm_dual(GDesc d0, GDesc d1, int split)
{
    extern __shared__ uint8_t sm8[];
    uint32_t smb;
    asm("{ .reg .u64 t; cvta.to.shared.u64 t, %1; cvt.u32.u64 %0, t; }" : "=r"(smb) : "l"(sm8));

    const bool first = (int)blockIdx.x < split;
    const GDesc d = first ? d0 : d1;
    const int idx = first ? blockIdx.x : (blockIdx.x - split);
    const int m0 = (idx / d.nbx) * BM;
    const int n0 = (idx % d.nbx) * BN;
    const int M = d.M, N = d.N, K = d.K;

    const int tid = threadIdx.x;
    const int lane = tid & 31, wm = tid >> 5;
    const int r = lane >> 2, cc = lane & 3;

    float acc[2][8][4];
    #pragma unroll
    for (int i = 0; i < 2; i++)
        #pragma unroll
        for (int j = 0; j < 8; j++)
            #pragma unroll
            for (int t = 0; t < 4; t++) acc[i][j][t] = 0.f;

    const int nst = K / BK;

    auto LOAD = [&](int s, int buf) {
        uint32_t base = smb + buf * STAGE_B;
        const int k0 = s * BK;
        #pragma unroll
        for (int i = 0; i < 4; i++) {
            int c = tid + i * 128;
            int row = c >> 2, col = c & 3;
            bool p = (m0 + row) < M;
            long g = (long)(p ? (m0 + row) : 0) * K + k0 + col * 8;
            uint32_t so = swz((uint32_t)(row * 64 + col * 16));
            cp16(base + so, d.A + g, p);
        }
        #pragma unroll
        for (int i = 0; i < 2; i++) {
            int c = tid + i * 128;
            int row = c >> 2, col = c & 3;
            bool p = (n0 + row) < N;
            long g = (long)(p ? (n0 + row) : 0) * K + k0 + col * 8;
            uint32_t so = swz((uint32_t)(row * 64 + col * 16));
            cp16(base + A_TILE_B + so, d.Bh + g, p);
            cp16(base + A_TILE_B + B_TILE_B + so, d.Bl + g, p);
        }
        asm volatile("cp.async.commit_group;\n" ::: "memory");
    };

    auto COMPUTE = [&](int buf) {
        uint32_t base = smb + buf * STAGE_B;
        #pragma unroll
        for (int kk = 0; kk < 2; kk++) {
            const uint32_t koff = (uint32_t)((kk * 2 + (lane >> 4)) * 16);
            uint32_t a[2][4];
            #pragma unroll
            for (int mt = 0; mt < 2; mt++) {
                int row = wm * 32 + mt * 16 + (lane & 15);
                ldsm4(a[mt], base + swz((uint32_t)(row * 64) + koff));
            }
            // double-buffered B fragments: prefetch nt2+1 before MMAs of nt2
            uint32_t bh[2][4], bl[2][4];
            {
                int row = (lane & 15);
                uint32_t off = swz((uint32_t)(row * 64) + koff);
                ldsm4(bh[0], base + A_TILE_B + off);
                ldsm4(bl[0], base + A_TILE_B + B_TILE_B + off);
            }
            #pragma unroll
            for (int nt2 = 0; nt2 < 4; nt2++) {
                const int cur = nt2 & 1, nxt = cur ^ 1;
                if (nt2 < 3) {
                    int row = (nt2 + 1) * 16 + (lane & 15);
                    uint32_t off = swz((uint32_t)(row * 64) + koff);
                    ldsm4(bh[nxt], base + A_TILE_B + off);
                    ldsm4(bl[nxt], base + A_TILE_B + B_TILE_B + off);
                }
                #pragma unroll
                for (int mt = 0; mt < 2; mt++)
                    #pragma unroll
                    for (int hv = 0; hv < 2; hv++) {
                        int nt = nt2 * 2 + hv;
                        MMAF16(acc[mt][nt], a[mt], bh[cur][hv], bh[cur][hv + 2]);
                        MMAF16(acc[mt][nt], a[mt], bl[cur][hv], bl[cur][hv + 2]);
                    }
            }
        }
    };

    LOAD(0, 0);
    if (nst > 1) LOAD(1, 1);
    for (int s = 0; s < nst; s++) {
        if (s + 1 < nst) { asm volatile("cp.async.wait_group 1;\n" ::: "memory"); }
        else             { asm volatile("cp.async.wait_group 0;\n" ::: "memory"); }
        __syncthreads();
        if (s + 2 < nst) LOAD(s + 2, (s + 2) % NSTAGE);
        COMPUTE(s % NSTAGE);
    }

    if (d.halfOut) {
        __half* C = (__half*)d.C;
        #pragma unroll
        for (int mt = 0; mt < 2; mt++) {
            int m = m0 + wm * 32 + mt * 16 + r;
            #pragma unroll
            for (int nt = 0; nt < 8; nt++) {
                int n = n0 + nt * 8 + cc * 2;
                const float* dd = acc[mt][nt];
                if (n + 1 < N) {
                    float b0 = d.bias[n], b1 = d.bias[n + 1];
                    if (m < M)
                        *(__half2*)&C[(long)m * N + n] = __floats2half2_rn(dd[0] + b0, dd[1] + b1);
                    if (m + 8 < M)
                        *(__half2*)&C[(long)(m + 8) * N + n] = __floats2half2_rn(dd[2] + b0, dd[3] + b1);
                } else if (n < N) {
                    float b0 = d.bias[n];
                    if (m < M)     C[(long)m * N + n]       = __float2half_rn(dd[0] + b0);
                    if (m + 8 < M) C[(long)(m + 8) * N + n] = __float2half_rn(dd[2] + b0);
                }
            }
        }
    } else {
        float* C = (float*)d.C;
        #pragma unroll
        for (int mt = 0; mt < 2; mt++) {
            int m = m0 + wm * 32 + mt * 16 + r;
            #pragma unroll
            for (int nt = 0; nt < 8; nt++) {
                int n = n0 + nt * 8 + cc * 2;
                const float* dd = acc[mt][nt];
                if (m < M) {
                    if (n < N)     C[(long)m * N + n]     = dd[0] + d.bias[n];
                    if (n + 1 < N) C[(long)m * N + n + 1] = dd[1] + d.bias[n + 1];
                }
                if (m + 8 < M) {
                    if (n < N)     C[(long)(m + 8) * N + n]     = dd[2] + d.bias[n];
                    if (n + 1 < N) C[(long)(m + 8) * N + n + 1] = dd[3] + d.bias[n + 1];
                }
            }
        }
    }
}

// ---------------- sampler: 4 samples per warp iteration, uint4 gathers ----------------
__global__ __launch_bounds__(192)
void sample_kernel(const float* __restrict__ coor,
                   const float* __restrict__ cam2img,
                   const float* __restrict__ lidar2cam)
{
    const int q = blockIdx.x;
    const int b = blockIdx.y;
    const int tid = threadIdx.x;
    const int h    = tid >> 5;
    const int lane = tid & 31;
    const int g    = lane >> 3;
    const int l8   = lane & 7;

    __shared__ float  s_uv[2];
    __shared__ float  s_logit[NH_][NL_*NP_];
    __shared__ float  s_w[NH_][28];
    __shared__ int4   s_idx[NH_][28];
    __shared__ float4 s_bw[NH_][28];

    if (tid == 0) {
        const float* L  = lidar2cam + b * 16;
        const float* Kc = cam2img + b * 16;
        float p0 = coor[((long)b * NQ_ + q) * 3 + 0];
        float p1 = coor[((long)b * NQ_ + q) * 3 + 1];
        float p2 = coor[((long)b * NQ_ + q) * 3 + 2];
        float pc[3], pr[3];
        #pragma unroll
        for (int i = 0; i < 3; i++)
            pc[i] = L[i*4+0]*p0 + L[i*4+1]*p1 + L[i*4+2]*p2 + L[i*4+3];
        #pragma unroll
        for (int i = 0; i < 3; i++)
            pr[i] = Kc[i*4+0]*pc[0] + Kc[i*4+1]*pc[1] + Kc[i*4+2]*pc[2] + Kc[i*4+3];
        s_uv[0] = pr[0] / pr[2];
        s_uv[1] = pr[1] / pr[2];
    }
    __syncthreads();

    const long bq = (long)b * NQ_ + q;
    const float* oa = g_oa + bq * NOA_;

    if (tid < NATT_) {
        const int hh = tid / (NL_*NP_);
        const int j  = tid - hh * (NL_*NP_);
        const int l = j / NP_;
        const int p = j - l * NP_;

        s_logit[hh][j] = oa[NOFF_ + hh * (NL_*NP_) + j];

        const float* offp = &oa[hh * (NL_*NP_*2) + l * (NP_*2) + p * 2];
        float px = s_uv[0] * c_SX[l] + offp[0] - 0.5f;
        float py = s_uv[1] * c_SY[l] + offp[1] - 0.5f;
        float x0 = floorf(px), y0 = floorf(py);
        float fx = px - x0, fy = py - y0;
        const int wl = c_W[l], hl = c_H[l];
        const int base_l = b * TOTHW_ + c_OFF[l];

        int   idv[4];
        float bwv[4];
        #pragma unroll
        for (int c = 0; c < 4; c++) {
            int dx = c & 1, dy = c >> 1;
            float xi = x0 + dx, yi = y0 + dy;
            bool valid = (xi >= 0.f) && (xi < (float)wl) && (yi >= 0.f) && (yi < (float)hl);
            float wgt = (dx ? fx : 1.f - fx) * (dy ? fy : 1.f - fy);
            float xc = fminf(fmaxf(xi, 0.f), (float)(wl - 1));
            float yc = fminf(fmaxf(yi, 0.f), (float)(hl - 1));
            int pix = (int)yc * wl + (int)xc;
            idv[c] = (base_l + pix) * NHD_ + hh * DH_;
            bwv[c] = valid ? wgt : 0.f;
        }
        s_idx[hh][j] = make_int4(idv[0], idv[1], idv[2], idv[3]);
        s_bw[hh][j]  = make_float4(bwv[0], bwv[1], bwv[2], bwv[3]);
    }
    __syncthreads();

    if (tid < NATT_) {
        const int hh = tid / (NL_*NP_);
        const int j  = tid - hh * (NL_*NP_);
        float mx = -1e30f;
        #pragma unroll
        for (int jj = 0; jj < NL_*NP_; jj++) mx = fmaxf(mx, s_logit[hh][jj]);
        s_w[hh][j] = expf(s_logit[hh][j] - mx);
    }
    if (tid < NH_) {
        s_w[tid][27]   = 0.f;
        s_idx[tid][27] = s_idx[tid][26];
        s_bw[tid][27]  = make_float4(0.f, 0.f, 0.f, 0.f);
    }
    __syncthreads();

    float sum = 0.f;
    #pragma unroll
    for (int jj = 0; jj < NL_*NP_; jj++) sum += s_w[h][jj];
    const float rsum = 1.f / sum;

    float a[8];
    #pragma unroll
    for (int k = 0; k < 8; k++) a[k] = 0.f;

    #pragma unroll
    for (int jp = 0; jp < 7; jp++) {
        const int j = jp * 4 + g;
        const float aw = s_w[h][j] * rsum;
        const int4   id = s_idx[h][j];
        const float4 bw = s_bw[h][j];
        const int ids[4] = {id.x, id.y, id.z, id.w};
        const float bws[4] = {bw.x, bw.y, bw.z, bw.w};
        float t[8];
        #pragma unroll
        for (int k = 0; k < 8; k++) t[k] = 0.f;
        #pragma unroll
        for (int c = 0; c < 4; c++) {
            uint4 u = *reinterpret_cast<const uint4*>(g_vh16 + ids[c] + l8 * 8);
            float w = bws[c];
            float2 f0 = __half22float2(*reinterpret_cast<__half2*>(&u.x));
            float2 f1 = __half22float2(*reinterpret_cast<__half2*>(&u.y));
            float2 f2 = __half22float2(*reinterpret_cast<__half2*>(&u.z));
            float2 f3 = __half22float2(*reinterpret_cast<__half2*>(&u.w));
            t[0] += w * f0.x; t[1] += w * f0.y;
            t[2] += w * f1.x; t[3] += w * f1.y;
            t[4] += w * f2.x; t[5] += w * f2.y;
            t[6] += w * f3.x; t[7] += w * f3.y;
        }
        #pragma unroll
        for (int k = 0; k < 8; k++) a[k] += aw * t[k];
    }

    #pragma unroll
    for (int k = 0; k < 8; k++) {
        a[k] += __shfl_xor_sync(0xffffffffu, a[k], 8);
        a[k] += __shfl_xor_sync(0xffffffffu, a[k], 16);
    }

    if (g == 0) {
        long oidx = bq * NHD_ + h * DH_ + l8 * 8;
        __half hv[8];
        #pragma unroll
        for (int k = 0; k < 8; k++) hv[k] = __float2half_rn(a[k]);
        *reinterpret_cast<uint4*>(&g_mid16[oidx]) = *reinterpret_cast<uint4*>(hv);
    }
}

// ---------------- host launcher ----------------
extern "C" void kernel_launch(void* const* d_in, const int* in_sizes, int n_in,
                              void* d_out, int out_size)
{
    const float* x         = (const float*)d_in[0];
    const float* pe        = (const float*)d_in[1];
    const float* coor      = (const float*)d_in[2];
    const float* cam2img   = (const float*)d_in[3];
    const float* lidar2cam = (const float*)d_in[4];
    const float* feat0     = (const float*)d_in[5];
    const float* feat1     = (const float*)d_in[6];
    const float* feat2     = (const float*)d_in[7];
    const float* W_value   = (const float*)d_in[8];
    const float* b_value   = (const float*)d_in[9];
    const float* W_off     = (const float*)d_in[10];
    const float* b_off     = (const float*)d_in[11];
    const float* W_attn    = (const float*)d_in[12];
    const float* b_attn    = (const float*)d_in[13];
    const float* W_out     = (const float*)d_in[14];
    const float* b_out     = (const float*)d_in[15];
    float* out = (float*)d_out;

    float *poa, *pboa;
    __half *pv16, *pq16, *pf16, *pmid16, *pwh, *pwl;
    cudaGetSymbolAddress((void**)&pv16, g_vh16);
    cudaGetSymbolAddress((void**)&poa, g_oa);
    cudaGetSymbolAddress((void**)&pboa, g_boa);
    cudaGetSymbolAddress((void**)&pq16, g_q16);
    cudaGetSymbolAddress((void**)&pf16, g_f16);
    cudaGetSymbolAddress((void**)&pmid16, g_mid16);
    cudaGetSymbolAddress((void**)&pwh, g_wh);
    cudaGetSymbolAddress((void**)&pwl, g_wl);

    static bool attrSet = false;
    if (!attrSet) {
        cudaFuncSetAttribute(f16_gemm_dual, cudaFuncAttributeMaxDynamicSharedMemorySize, GEMM_SMEM);
        attrSet = true;
    }

    // 1: weight transposes + bias concat
    {
        dim3 grid(12, 12, 5);
        prep_weights_kernel<<<grid, 256>>>(W_value, W_off, W_attn, W_out, b_off, b_attn);
    }
    // 2: q = x + pe (fp16)
    {
        int n4 = B_ * NQ_ * DM_ / 4;
        add_half_kernel<<<(n4 + 255) / 256, 256>>>(x, pe, pq16, n4);
    }
    // 3: fused feature transpose (fp16)
    {
        dim3 grid(315, 8, B_);
        feat_transpose_kernel<<<grid, 256>>>(feat0, feat1, feat2);
    }
    // 4: fused value + offsets/attn GEMMs (one launch)
    {
        GDesc dv;  // value: [B*TOTHW, 384] = f16 @ Wv
        dv.A = pf16; dv.Bh = pwh + WV_OFF; dv.Bl = pwl + WV_OFF;
        dv.bias = b_value; dv.C = pv16;
        dv.M = B_ * TOTHW_; dv.N = NHD_; dv.K = DM_; dv.halfOut = 1;
        dv.nbx = NHD_ / BN;  // 6
        int nv = dv.nbx * ((dv.M + BM - 1) / BM);   // 6*158 = 948

        GDesc doa; // offsets+attn: [B*NQ, 486] = q16 @ Woa
        doa.A = pq16; doa.Bh = pwh + WOA_OFF; doa.Bl = pwl + WOA_OFF;
        doa.bias = pboa; doa.C = poa;
        doa.M = B_ * NQ_; doa.N = NOA_; doa.K = DM_; doa.halfOut = 0;
        doa.nbx = (NOA_ + BN - 1) / BN;  // 8
        int noa = doa.nbx * (doa.M / BM);            // 8*128 = 1024

        f16_gemm_dual<<<nv + noa, 128, GEMM_SMEM>>>(dv, doa, nv);
    }
    // 5: sampler
    {
        dim3 grid(NQ_, B_);
        sample_kernel<<<grid, 192>>>(coor, cam2img, lidar2cam);
    }
    // 6: output GEMM
    {
        GDesc dn;
        dn.A = pmid16; dn.Bh = pwh + WOUT_OFF; dn.Bl = pwl + WOUT_OFF;
        dn.bias = b_out; dn.C = out;
        dn.M = B_ * NQ_; dn.N = DM_; dn.K = NHD_; dn.halfOut = 0;
        dn.nbx = DM_ / BN;  // 4
        int nb = dn.nbx * (dn.M / BM);  // 512
        f16_gemm_dual<<<nb, 128, GEMM_SMEM>>>(dn, dn, nb);
    }
}

// round 13
// speedup vs baseline: 2.0934x; 1.1168x over previous
#include <cuda_runtime.h>
#include <cuda_bf16.h>
#include <cuda_fp16.h>
#include <math.h>
#include <stdint.h>

// ---------------- problem constants ----------------
#define B_   2
#define NQ_  8192
#define DM_  256
#define NH_  6
#define DH_  64
#define NL_  3
#define NP_  9
#define NHD_ (NH_*DH_)            // 384
#define NOFF_ (NH_*NL_*NP_*2)     // 324
#define NATT_ (NH_*NL_*NP_)       // 162
#define NOA_  (NOFF_ + NATT_)     // 486
#define TOTHW_ 10080              // 7680+1920+480

// level tables
__device__ __constant__ int   c_W[3]   = {160, 80, 40};
__device__ __constant__ int   c_H[3]   = {48, 24, 12};
__device__ __constant__ int   c_OFF[3] = {0, 7680, 9600};
__device__ __constant__ float c_SX[3]  = {160.f/1280.f, 80.f/1280.f, 40.f/1280.f};
__device__ __constant__ float c_SY[3]  = {48.f/384.f, 24.f/384.f, 12.f/384.f};

// ---------------- scratch (no allocs allowed) ----------------
__device__ __half g_vh16[(size_t)B_ * TOTHW_ * NHD_];   // value projection (fp16)
__device__ float g_oa  [(size_t)B_ * NQ_ * NOA_];       // offsets(324) | attn(162)
__device__ float g_boa [NOA_];

// single fp16 A-planes
__device__ __half g_q16 [(size_t)B_ * NQ_ * DM_];
__device__ __half g_f16 [(size_t)B_ * TOTHW_ * DM_];
__device__ __half g_mid16[(size_t)B_ * NQ_ * NHD_];

// weights transposed [N][K] fp16: Wv(384x256) | Woa(486x256) | Wout(256x384)
#define WV_OFF   0
#define WOA_OFF  (384*256)
#define WOUT_OFF (WOA_OFF + NOA_*256)
#define WTOT_    (WOUT_OFF + 256*384)
__device__ __half g_wh[WTOT_];

// ================= prep kernels =================
__global__ __launch_bounds__(256)
void add_half_kernel(const float* __restrict__ x, const float* __restrict__ pe,
                     __half* __restrict__ o, int n4)
{
    int i = blockIdx.x * blockDim.x + threadIdx.x;
    if (i >= n4) return;
    float4 a = reinterpret_cast<const float4*>(x)[i];
    float4 b = reinterpret_cast<const float4*>(pe)[i];
    __half h[4];
    h[0] = __float2half_rn(a.x + b.x);
    h[1] = __float2half_rn(a.y + b.y);
    h[2] = __float2half_rn(a.z + b.z);
    h[3] = __float2half_rn(a.w + b.w);
    *reinterpret_cast<uint2*>(o + (size_t)i*4) = *reinterpret_cast<uint2*>(h);
}

// fused feature transpose: all 3 levels, both batches -> fp16 [b][pix][256]
__global__ __launch_bounds__(256)
void feat_transpose_kernel(const float* __restrict__ f0, const float* __restrict__ f1,
                           const float* __restrict__ f2)
{
    __shared__ float t[32][33];
    const int b = blockIdx.z;
    int xt = blockIdx.x;
    int l, c0;
    const float* in;
    int hwl;
    if (xt < 240)      { l = 0; c0 = xt * 32;         in = f0; hwl = 7680; }
    else if (xt < 300) { l = 1; c0 = (xt - 240) * 32; in = f1; hwl = 1920; }
    else               { l = 2; c0 = (xt - 300) * 32; in = f2; hwl = 480;  }
    in += (long)b * DM_ * hwl;
    const int r0 = blockIdx.y * 32;
    const int tx = threadIdx.x & 31, ty = threadIdx.x >> 5;

    #pragma unroll
    for (int i = 0; i < 32; i += 8)
        t[ty + i][tx] = in[(long)(r0 + ty + i) * hwl + c0 + tx];
    __syncthreads();
    const long outBase = ((long)b * TOTHW_ + c_OFF[l] + c0) * DM_ + r0;
    #pragma unroll
    for (int i = 0; i < 32; i += 8) {
        long o = outBase + (long)(ty + i) * DM_ + tx;
        g_f16[o] = __float2half_rn(t[tx][ty + i]);
    }
}

// weight transposes (fp16) + bias concat
__global__ __launch_bounds__(256)
void prep_weights_kernel(const float* __restrict__ Wv, const float* __restrict__ Woff,
                         const float* __restrict__ Wattn, const float* __restrict__ Wout,
                         const float* __restrict__ boff, const float* __restrict__ battn)
{
    const int z = blockIdx.z;
    if (z == 4) {
        if (blockIdx.y != 0 || blockIdx.x > 1) return;
        int i = blockIdx.x * 256 + threadIdx.x;
        if (i < NOFF_) g_boa[i] = boff[i];
        else if (i < NOA_) g_boa[i] = battn[i - NOFF_];
        return;
    }
    int R, C; const float* in; long base; int rowOff = 0;
    if (z == 0)      { in = Wv;    R = 256; C = 384; base = WV_OFF; }
    else if (z == 1) { in = Woff;  R = 256; C = 324; base = WOA_OFF; }
    else if (z == 2) { in = Wattn; R = 256; C = 162; base = WOA_OFF; rowOff = 324; }
    else             { in = Wout;  R = 384; C = 256; base = WOUT_OFF; }

    const int c0 = blockIdx.x * 32, r0 = blockIdx.y * 32;
    if (c0 >= C || r0 >= R) return;

    __shared__ float t[32][33];
    const int tx = threadIdx.x & 31, ty = threadIdx.x >> 5;
    #pragma unroll
    for (int i = 0; i < 32; i += 8) {
        int r = r0 + ty + i, c = c0 + tx;
        t[ty + i][tx] = (r < R && c < C) ? in[(long)r * C + c] : 0.f;
    }
    __syncthreads();
    #pragma unroll
    for (int i = 0; i < 32; i += 8) {
        int c = c0 + ty + i, r = r0 + tx;
        if (c < C && r < R)
            g_wh[base + (long)(rowOff + c) * R + r] = __float2half_rn(t[tx][ty + i]);
    }
}

// ================= fp16 tensor-core GEMM (dual-descriptor, single B plane) =================
#define BM 128
#define BN 64
#define BK 32
#define A_TILE_B (BM*BK*2)                 // 8192
#define B_TILE_B (BN*BK*2)                 // 4096
#define STAGE_B  (A_TILE_B + B_TILE_B)     // 12288
#define NSTAGE 3
#define GEMM_SMEM (NSTAGE*STAGE_B)         // 36864

struct GDesc {
    const __half* A;
    const __half* Bh;
    const float*  bias;
    void*         C;
    int M, N, K, halfOut, nbx;
};

#define MMAF16(d, a, b0v, b1v) \
  asm volatile("mma.sync.aligned.m16n8k16.row.col.f32.f16.f16.f32 " \
    "{%0,%1,%2,%3},{%4,%5,%6,%7},{%8,%9},{%0,%1,%2,%3};" \
    : "+f"((d)[0]), "+f"((d)[1]), "+f"((d)[2]), "+f"((d)[3]) \
    : "r"((a)[0]), "r"((a)[1]), "r"((a)[2]), "r"((a)[3]), "r"(b0v), "r"(b1v))

__device__ __forceinline__ uint32_t swz(uint32_t off) {
    return off ^ ((off >> 3) & 0x30);
}
__device__ __forceinline__ void ldsm4(uint32_t (&r)[4], uint32_t addr) {
    asm volatile("ldmatrix.sync.aligned.m8n8.x4.shared.b16 {%0,%1,%2,%3}, [%4];"
        : "=r"(r[0]), "=r"(r[1]), "=r"(r[2]), "=r"(r[3]) : "r"(addr));
}
__device__ __forceinline__ void cp16(uint32_t dst, const void* src, bool pred) {
    int sz = pred ? 16 : 0;
    asm volatile("cp.async.cg.shared.global [%0], [%1], 16, %2;\n"
                 :: "r"(dst), "l"(src), "r"(sz));
}

__global__ __launch_bounds__(128, 4)
void f16_gemm_dual(GDesc d0, GDesc d1, int split)
{
    extern __shared__ uint8_t sm8[];
    uint32_t smb;
    asm("{ .reg .u64 t; cvta.to.shared.u64 t, %1; cvt.u32.u64 %0, t; }" : "=r"(smb) : "l"(sm8));

    const bool first = (int)blockIdx.x < split;
    const GDesc d = first ? d0 : d1;
    const int idx = first ? blockIdx.x : (blockIdx.x - split);
    const int m0 = (idx / d.nbx) * BM;
    const int n0 = (idx % d.nbx) * BN;
    const int M = d.M, N = d.N, K = d.K;

    const int tid = threadIdx.x;
    const int lane = tid & 31, wm = tid >> 5;
    const int r = lane >> 2, cc = lane & 3;

    float acc[2][8][4];
    #pragma unroll
    for (int i = 0; i < 2; i++)
        #pragma unroll
        for (int j = 0; j < 8; j++)
            #pragma unroll
            for (int t = 0; t < 4; t++) acc[i][j][t] = 0.f;

    const int nst = K / BK;

    auto LOAD = [&](int s, int buf) {
        uint32_t base = smb + buf * STAGE_B;
        const int k0 = s * BK;
        #pragma unroll
        for (int i = 0; i < 4; i++) {
            int c = tid + i * 128;
            int row = c >> 2, col = c & 3;
            bool p = (m0 + row) < M;
            long g = (long)(p ? (m0 + row) : 0) * K + k0 + col * 8;
            uint32_t so = swz((uint32_t)(row * 64 + col * 16));
            cp16(base + so, d.A + g, p);
        }
        #pragma unroll
        for (int i = 0; i < 2; i++) {
            int c = tid + i * 128;
            int row = c >> 2, col = c & 3;
            bool p = (n0 + row) < N;
            long g = (long)(p ? (n0 + row) : 0) * K + k0 + col * 8;
            uint32_t so = swz((uint32_t)(row * 64 + col * 16));
            cp16(base + A_TILE_B + so, d.Bh + g, p);
        }
        asm volatile("cp.async.commit_group;\n" ::: "memory");
    };

    auto COMPUTE = [&](int buf) {
        uint32_t base = smb + buf * STAGE_B;
        #pragma unroll
        for (int kk = 0; kk < 2; kk++) {
            const uint32_t koff = (uint32_t)((kk * 2 + (lane >> 4)) * 16);
            uint32_t a[2][4];
            #pragma unroll
            for (int mt = 0; mt < 2; mt++) {
                int row = wm * 32 + mt * 16 + (lane & 15);
                ldsm4(a[mt], base + swz((uint32_t)(row * 64) + koff));
            }
            // double-buffered B fragments: prefetch nt2+1 before MMAs of nt2
            uint32_t bh[2][4];
            {
                int row = (lane & 15);
                ldsm4(bh[0], base + A_TILE_B + swz((uint32_t)(row * 64) + koff));
            }
            #pragma unroll
            for (int nt2 = 0; nt2 < 4; nt2++) {
                const int cur = nt2 & 1, nxt = cur ^ 1;
                if (nt2 < 3) {
                    int row = (nt2 + 1) * 16 + (lane & 15);
                    ldsm4(bh[nxt], base + A_TILE_B + swz((uint32_t)(row * 64) + koff));
                }
                #pragma unroll
                for (int mt = 0; mt < 2; mt++)
                    #pragma unroll
                    for (int hv = 0; hv < 2; hv++) {
                        int nt = nt2 * 2 + hv;
                        MMAF16(acc[mt][nt], a[mt], bh[cur][hv], bh[cur][hv + 2]);
                    }
            }
        }
    };

    LOAD(0, 0);
    if (nst > 1) LOAD(1, 1);
    for (int s = 0; s < nst; s++) {
        if (s + 1 < nst) { asm volatile("cp.async.wait_group 1;\n" ::: "memory"); }
        else             { asm volatile("cp.async.wait_group 0;\n" ::: "memory"); }
        __syncthreads();
        if (s + 2 < nst) LOAD(s + 2, (s + 2) % NSTAGE);
        COMPUTE(s % NSTAGE);
    }

    if (d.halfOut) {
        __half* C = (__half*)d.C;
        #pragma unroll
        for (int mt = 0; mt < 2; mt++) {
            int m = m0 + wm * 32 + mt * 16 + r;
            #pragma unroll
            for (int nt = 0; nt < 8; nt++) {
                int n = n0 + nt * 8 + cc * 2;
                const float* dd = acc[mt][nt];
                if (n + 1 < N) {
                    float b0 = d.bias[n], b1 = d.bias[n + 1];
                    if (m < M)
                        *(__half2*)&C[(long)m * N + n] = __floats2half2_rn(dd[0] + b0, dd[1] + b1);
                    if (m + 8 < M)
                        *(__half2*)&C[(long)(m + 8) * N + n] = __floats2half2_rn(dd[2] + b0, dd[3] + b1);
                } else if (n < N) {
                    float b0 = d.bias[n];
                    if (m < M)     C[(long)m * N + n]       = __float2half_rn(dd[0] + b0);
                    if (m + 8 < M) C[(long)(m + 8) * N + n] = __float2half_rn(dd[2] + b0);
                }
            }
        }
    } else {
        float* C = (float*)d.C;
        #pragma unroll
        for (int mt = 0; mt < 2; mt++) {
            int m = m0 + wm * 32 + mt * 16 + r;
            #pragma unroll
            for (int nt = 0; nt < 8; nt++) {
                int n = n0 + nt * 8 + cc * 2;
                const float* dd = acc[mt][nt];
                if (m < M) {
                    if (n < N)     C[(long)m * N + n]     = dd[0] + d.bias[n];
                    if (n + 1 < N) C[(long)m * N + n + 1] = dd[1] + d.bias[n + 1];
                }
                if (m + 8 < M) {
                    if (n < N)     C[(long)(m + 8) * N + n]     = dd[2] + d.bias[n];
                    if (n + 1 < N) C[(long)(m + 8) * N + n + 1] = dd[3] + d.bias[n + 1];
                }
            }
        }
    }
}

// ---------------- sampler: 4 samples per warp iteration, uint4 gathers ----------------
__global__ __launch_bounds__(192)
void sample_kernel(const float* __restrict__ coor,
                   const float* __restrict__ cam2img,
                   const float* __restrict__ lidar2cam)
{
    const int q = blockIdx.x;
    const int b = blockIdx.y;
    const int tid = threadIdx.x;
    const int h    = tid >> 5;
    const int lane = tid & 31;
    const int g    = lane >> 3;
    const int l8   = lane & 7;

    __shared__ float  s_uv[2];
    __shared__ float  s_logit[NH_][NL_*NP_];
    __shared__ float  s_w[NH_][28];
    __shared__ int4   s_idx[NH_][28];
    __shared__ float4 s_bw[NH_][28];

    if (tid == 0) {
        const float* L  = lidar2cam + b * 16;
        const float* Kc = cam2img + b * 16;
        float p0 = coor[((long)b * NQ_ + q) * 3 + 0];
        float p1 = coor[((long)b * NQ_ + q) * 3 + 1];
        float p2 = coor[((long)b * NQ_ + q) * 3 + 2];
        float pc[3], pr[3];
        #pragma unroll
        for (int i = 0; i < 3; i++)
            pc[i] = L[i*4+0]*p0 + L[i*4+1]*p1 + L[i*4+2]*p2 + L[i*4+3];
        #pragma unroll
        for (int i = 0; i < 3; i++)
            pr[i] = Kc[i*4+0]*pc[0] + Kc[i*4+1]*pc[1] + Kc[i*4+2]*pc[2] + Kc[i*4+3];
        s_uv[0] = pr[0] / pr[2];
        s_uv[1] = pr[1] / pr[2];
    }
    __syncthreads();

    const long bq = (long)b * NQ_ + q;
    const float* oa = g_oa + bq * NOA_;

    if (tid < NATT_) {
        const int hh = tid / (NL_*NP_);
        const int j  = tid - hh * (NL_*NP_);
        const int l = j / NP_;
        const int p = j - l * NP_;

        s_logit[hh][j] = oa[NOFF_ + hh * (NL_*NP_) + j];

        const float* offp = &oa[hh * (NL_*NP_*2) + l * (NP_*2) + p * 2];
        float px = s_uv[0] * c_SX[l] + offp[0] - 0.5f;
        float py = s_uv[1] * c_SY[l] + offp[1] - 0.5f;
        float x0 = floorf(px), y0 = floorf(py);
        float fx = px - x0, fy = py - y0;
        const int wl = c_W[l], hl = c_H[l];
        const int base_l = b * TOTHW_ + c_OFF[l];

        int   idv[4];
        float bwv[4];
        #pragma unroll
        for (int c = 0; c < 4; c++) {
            int dx = c & 1, dy = c >> 1;
            float xi = x0 + dx, yi = y0 + dy;
            bool valid = (xi >= 0.f) && (xi < (float)wl) && (yi >= 0.f) && (yi < (float)hl);
            float wgt = (dx ? fx : 1.f - fx) * (dy ? fy : 1.f - fy);
            float xc = fminf(fmaxf(xi, 0.f), (float)(wl - 1));
            float yc = fminf(fmaxf(yi, 0.f), (float)(hl - 1));
            int pix = (int)yc * wl + (int)xc;
            idv[c] = (base_l + pix) * NHD_ + hh * DH_;
            bwv[c] = valid ? wgt : 0.f;
        }
        s_idx[hh][j] = make_int4(idv[0], idv[1], idv[2], idv[3]);
        s_bw[hh][j]  = make_float4(bwv[0], bwv[1], bwv[2], bwv[3]);
    }
    __syncthreads();

    if (tid < NATT_) {
        const int hh = tid / (NL_*NP_);
        const int j  = tid - hh * (NL_*NP_);
        float mx = -1e30f;
        #pragma unroll
        for (int jj = 0; jj < NL_*NP_; jj++) mx = fmaxf(mx, s_logit[hh][jj]);
        s_w[hh][j] = expf(s_logit[hh][j] - mx);
    }
    if (tid < NH_) {
        s_w[tid][27]   = 0.f;
        s_idx[tid][27] = s_idx[tid][26];
        s_bw[tid][27]  = make_float4(0.f, 0.f, 0.f, 0.f);
    }
    __syncthreads();

    float sum = 0.f;
    #pragma unroll
    for (int jj = 0; jj < NL_*NP_; jj++) sum += s_w[h][jj];
    const float rsum = 1.f / sum;

    float a[8];
    #pragma unroll
    for (int k = 0; k < 8; k++) a[k] = 0.f;

    #pragma unroll
    for (int jp = 0; jp < 7; jp++) {
        const int j = jp * 4 + g;
        const float aw = s_w[h][j] * rsum;
        const int4   id = s_idx[h][j];
        const float4 bw = s_bw[h][j];
        const int ids[4] = {id.x, id.y, id.z, id.w};
        const float bws[4] = {bw.x, bw.y, bw.z, bw.w};
        float t[8];
        #pragma unroll
        for (int k = 0; k < 8; k++) t[k] = 0.f;
        #pragma unroll
        for (int c = 0; c < 4; c++) {
            uint4 u = *reinterpret_cast<const uint4*>(g_vh16 + ids[c] + l8 * 8);
            float w = bws[c];
            float2 f0 = __half22float2(*reinterpret_cast<__half2*>(&u.x));
            float2 f1 = __half22float2(*reinterpret_cast<__half2*>(&u.y));
            float2 f2 = __half22float2(*reinterpret_cast<__half2*>(&u.z));
            float2 f3 = __half22float2(*reinterpret_cast<__half2*>(&u.w));
            t[0] += w * f0.x; t[1] += w * f0.y;
            t[2] += w * f1.x; t[3] += w * f1.y;
            t[4] += w * f2.x; t[5] += w * f2.y;
            t[6] += w * f3.x; t[7] += w * f3.y;
        }
        #pragma unroll
        for (int k = 0; k < 8; k++) a[k] += aw * t[k];
    }

    #pragma unroll
    for (int k = 0; k < 8; k++) {
        a[k] += __shfl_xor_sync(0xffffffffu, a[k], 8);
        a[k] += __shfl_xor_sync(0xffffffffu, a[k], 16);
    }

    if (g == 0) {
        long oidx = bq * NHD_ + h * DH_ + l8 * 8;
        __half hv[8];
        #pragma unroll
        for (int k = 0; k < 8; k++) hv[k] = __float2half_rn(a[k]);
        *reinterpret_cast<uint4*>(&g_mid16[oidx]) = *reinterpret_cast<uint4*>(hv);
    }
}

// ---------------- host launcher ----------------
extern "C" void kernel_launch(void* const* d_in, const int* in_sizes, int n_in,
                              void* d_out, int out_size)
{
    const float* x         = (const float*)d_in[0];
    const float* pe        = (const float*)d_in[1];
    const float* coor      = (const float*)d_in[2];
    const float* cam2img   = (const float*)d_in[3];
    const float* lidar2cam = (const float*)d_in[4];
    const float* feat0     = (const float*)d_in[5];
    const float* feat1     = (const float*)d_in[6];
    const float* feat2     = (const float*)d_in[7];
    const float* W_value   = (const float*)d_in[8];
    const float* b_value   = (const float*)d_in[9];
    const float* W_off     = (const float*)d_in[10];
    const float* b_off     = (const float*)d_in[11];
    const float* W_attn    = (const float*)d_in[12];
    const float* b_attn    = (const float*)d_in[13];
    const float* W_out     = (const float*)d_in[14];
    const float* b_out     = (const float*)d_in[15];
    float* out = (float*)d_out;

    float *poa, *pboa;
    __half *pv16, *pq16, *pf16, *pmid16, *pwh;
    cudaGetSymbolAddress((void**)&pv16, g_vh16);
    cudaGetSymbolAddress((void**)&poa, g_oa);
    cudaGetSymbolAddress((void**)&pboa, g_boa);
    cudaGetSymbolAddress((void**)&pq16, g_q16);
    cudaGetSymbolAddress((void**)&pf16, g_f16);
    cudaGetSymbolAddress((void**)&pmid16, g_mid16);
    cudaGetSymbolAddress((void**)&pwh, g_wh);

    static bool attrSet = false;
    if (!attrSet) {
        cudaFuncSetAttribute(f16_gemm_dual, cudaFuncAttributeMaxDynamicSharedMemorySize, GEMM_SMEM);
        attrSet = true;
    }

    // 1: weight transposes + bias concat
    {
        dim3 grid(12, 12, 5);
        prep_weights_kernel<<<grid, 256>>>(W_value, W_off, W_attn, W_out, b_off, b_attn);
    }
    // 2: q = x + pe (fp16)
    {
        int n4 = B_ * NQ_ * DM_ / 4;
        add_half_kernel<<<(n4 + 255) / 256, 256>>>(x, pe, pq16, n4);
    }
    // 3: fused feature transpose (fp16)
    {
        dim3 grid(315, 8, B_);
        feat_transpose_kernel<<<grid, 256>>>(feat0, feat1, feat2);
    }
    // 4: fused value + offsets/attn GEMMs (one launch)
    {
        GDesc dv;  // value: [B*TOTHW, 384] = f16 @ Wv
        dv.A = pf16; dv.Bh = pwh + WV_OFF;
        dv.bias = b_value; dv.C = pv16;
        dv.M = B_ * TOTHW_; dv.N = NHD_; dv.K = DM_; dv.halfOut = 1;
        dv.nbx = NHD_ / BN;  // 6
        int nv = dv.nbx * ((dv.M + BM - 1) / BM);   // 948

        GDesc doa; // offsets+attn: [B*NQ, 486] = q16 @ Woa
        doa.A = pq16; doa.Bh = pwh + WOA_OFF;
        doa.bias = pboa; doa.C = poa;
        doa.M = B_ * NQ_; doa.N = NOA_; doa.K = DM_; doa.halfOut = 0;
        doa.nbx = (NOA_ + BN - 1) / BN;  // 8
        int noa = doa.nbx * (doa.M / BM);            // 1024

        f16_gemm_dual<<<nv + noa, 128, GEMM_SMEM>>>(dv, doa, nv);
    }
    // 5: sampler
    {
        dim3 grid(NQ_, B_);
        sample_kernel<<<grid, 192>>>(coor, cam2img, lidar2cam);
    }
    // 6: output GEMM
    {
        GDesc dn;
        dn.A = pmid16; dn.Bh = pwh + WOUT_OFF;
        dn.bias = b_out; dn.C = out;
        dn.M = B_ * NQ_; dn.N = DM_; dn.K = NHD_; dn.halfOut = 0;
        dn.nbx = DM_ / BN;  // 4
        int nb = dn.nbx * (dn.M / BM);  // 512
        f16_gemm_dual<<<nb, 128, GEMM_SMEM>>>(dn, dn, nb);
    }
}